// round 3
// baseline (speedup 1.0000x reference)
#include <cuda_runtime.h>
#include <cuda_bf16.h>
#include <math.h>
#include <stdint.h>

#define NN   100000
#define EE   1600000
#define FIN  128
#define HD   256
#define NHID_ 512
#define NOUT_ 256
#define GG   256

__device__ __forceinline__ uint32_t smem_u32(const void* p) {
    uint32_t a;
    asm("{ .reg .u64 t; cvta.to.shared.u64 t, %1; cvt.u32.u64 %0, t; }" : "=r"(a) : "l"(p));
    return a;
}

// ---------------- scratch (no allocation allowed) ----------------
__device__ __align__(256) float g_t[(size_t)NN * HD];      // GEMM out / SpMM in
__device__ __align__(256) float g_h[(size_t)NN * HD];      // activations
__device__ __align__(256) __nv_bfloat16 g_a3[(size_t)NN * 3 * HD];   // packed split A [M, 3K]
__device__ __align__(256) __nv_bfloat16 g_b3[3][HD * 3 * HD];        // packed split W^T [256, 3K]
__device__ int   g_deg[NN];
__device__ float g_dinv[NN];
__device__ int   g_rowoff[NN + 1];
__device__ int   g_cursor[NN];
__device__ int   g_col[EE];
__device__ float g_w[EE];
__device__ int   g_gstart[GG + 1];
__device__ float g_pooled[GG * HD];
__device__ float g_mlp1[GG * NHID_];

// ---------------- CSR construction ----------------
__global__ void zero_deg_kernel() {
    int i = blockIdx.x * blockDim.x + threadIdx.x;
    if (i < NN) g_deg[i] = 0;
}

__global__ void count_kernel(const int* __restrict__ dst) {
    int e = blockIdx.x * blockDim.x + threadIdx.x;
    if (e < EE) atomicAdd(&g_deg[dst[e]], 1);
}

__global__ void scan_kernel() {
    __shared__ int sh[1024];
    __shared__ int carry;
    int tid = threadIdx.x;
    if (tid == 0) carry = 0;
    __syncthreads();
    for (int base = 0; base < NN; base += 1024) {
        int i = base + tid;
        int v = (i < NN) ? g_deg[i] : 0;
        sh[tid] = v;
        __syncthreads();
        for (int off = 1; off < 1024; off <<= 1) {
            int t = (tid >= off) ? sh[tid - off] : 0;
            __syncthreads();
            sh[tid] += t;
            __syncthreads();
        }
        int excl = carry + sh[tid] - v;
        if (i < NN) { g_rowoff[i] = excl; g_cursor[i] = excl; }
        __syncthreads();
        if (tid == 1023) carry += sh[1023];
        __syncthreads();
    }
    if (tid == 0) g_rowoff[NN] = carry;
}

__global__ void dinv_kernel() {
    int i = blockIdx.x * blockDim.x + threadIdx.x;
    if (i < NN) g_dinv[i] = rsqrtf(1.0f + (float)g_deg[i]);
}

__global__ void scatter_kernel(const int* __restrict__ src, const int* __restrict__ dst) {
    int e = blockIdx.x * blockDim.x + threadIdx.x;
    if (e < EE) {
        int s = src[e];
        int p = atomicAdd(&g_cursor[dst[e]], 1);
        g_col[p] = s;
        g_w[p] = g_dinv[s];
    }
}

// ---------------- hi/lo split + pack (K' = 3K) ----------------
// A [M,K] fp32 -> A3 [M,3K] bf16: [hi | hi | lo]
__global__ void splitA_kernel(const float* __restrict__ A,
                              __nv_bfloat16* __restrict__ A3, int M, int K) {
    int idx = blockIdx.x * blockDim.x + threadIdx.x;
    int half = K >> 1;
    if (idx >= M * half) return;
    int m = idx / half;
    int kk = (idx - m * half) * 2;
    float2 a = *(const float2*)(A + (size_t)m * K + kk);
    __nv_bfloat16 hx = __float2bfloat16(a.x);
    __nv_bfloat16 hy = __float2bfloat16(a.y);
    __nv_bfloat162 hp; hp.x = hx; hp.y = hy;
    __nv_bfloat162 lp;
    lp.x = __float2bfloat16(a.x - __bfloat162float(hx));
    lp.y = __float2bfloat16(a.y - __bfloat162float(hy));
    __nv_bfloat16* row = A3 + (size_t)m * (3 * K);
    *(__nv_bfloat162*)(row + kk)         = hp;
    *(__nv_bfloat162*)(row + K + kk)     = hp;
    *(__nv_bfloat162*)(row + 2 * K + kk) = lp;
}

// W [K,N] fp32 -> B3 [N,3K] bf16 rows: [hi | lo | hi]  (transposed)
__global__ void splitW_kernel(const float* __restrict__ W,
                              __nv_bfloat16* __restrict__ B3, int K, int N) {
    int idx = blockIdx.x * blockDim.x + threadIdx.x;
    if (idx >= K * N) return;
    int k = idx / N, n = idx % N;
    float w = W[idx];
    __nv_bfloat16 hi = __float2bfloat16(w);
    __nv_bfloat16 lo = __float2bfloat16(w - __bfloat162float(hi));
    __nv_bfloat16* row = B3 + (size_t)n * (3 * K);
    row[k]         = hi;
    row[K + k]     = lo;
    row[2 * K + k] = hi;
}

// ---------------- bf16 mma.sync GEMM: C[M,256] = A3[M,K3] @ B3[256,K3]^T ----------------
// BM=128, BN=128, BK=32, 256 threads (8 warps, warp tile 32x64), cp.async double buffer.
__global__ void __launch_bounds__(256, 1)
gemm_mma_kernel(const __nv_bfloat16* __restrict__ A3,
                const __nv_bfloat16* __restrict__ B3,
                float* __restrict__ C, int M, int K3)
{
    __shared__ __nv_bfloat16 As[2][128][40];
    __shared__ __nv_bfloat16 Bs[2][128][40];

    const int tid  = threadIdx.x;
    const int wid  = tid >> 5;
    const int lane = tid & 31;
    const int m0 = blockIdx.y * 128;
    const int n0 = blockIdx.x * 128;
    const int wm = (wid >> 1) * 32;    // 0,32,64,96
    const int wn = (wid & 1) * 64;     // 0,64

    float acc[2][8][4];
#pragma unroll
    for (int i = 0; i < 2; i++)
#pragma unroll
        for (int j = 0; j < 8; j++)
#pragma unroll
            for (int q = 0; q < 4; q++) acc[i][j][q] = 0.0f;

    const int NKB = K3 / 32;

    auto load_stage = [&](int kb, int buf) {
        int k0 = kb * 32;
#pragma unroll
        for (int it = 0; it < 2; it++) {
            int u = tid + it * 256;
            int row = u >> 2, kc = u & 3;
            const __nv_bfloat16* gp = A3 + (size_t)(m0 + row) * K3 + k0 + kc * 8;
            uint32_t d = smem_u32(&As[buf][row][kc * 8]);
            uint32_t sz = (m0 + row < M) ? 16u : 0u;
            asm volatile("cp.async.cg.shared.global [%0], [%1], 16, %2;"
                         :: "r"(d), "l"(gp), "r"(sz) : "memory");
        }
#pragma unroll
        for (int it = 0; it < 2; it++) {
            int u = tid + it * 256;
            int row = u >> 2, kc = u & 3;
            const __nv_bfloat16* gp = B3 + (size_t)(n0 + row) * K3 + k0 + kc * 8;
            uint32_t d = smem_u32(&Bs[buf][row][kc * 8]);
            asm volatile("cp.async.cg.shared.global [%0], [%1], 16;"
                         :: "r"(d), "l"(gp) : "memory");
        }
        asm volatile("cp.async.commit_group;" ::: "memory");
    };

    load_stage(0, 0);

    const int tg = lane >> 3;   // 0..3 (ldmatrix group)
    const int tr = lane & 7;    // row within group

    for (int kb = 0; kb < NKB; kb++) {
        int buf = kb & 1;
        if (kb + 1 < NKB) {
            load_stage(kb + 1, buf ^ 1);
            asm volatile("cp.async.wait_group 1;" ::: "memory");
        } else {
            asm volatile("cp.async.wait_group 0;" ::: "memory");
        }
        __syncthreads();

#pragma unroll
        for (int ks = 0; ks < 2; ks++) {
            int kb16 = ks * 16;
            // A fragments: 2 x (16x16) via ldmatrix.x4
            uint32_t a[2][4];
#pragma unroll
            for (int mi = 0; mi < 2; mi++) {
                uint32_t addr = smem_u32(
                    &As[buf][wm + mi * 16 + tr + (tg & 1) * 8][kb16 + (tg >> 1) * 8]);
                asm volatile("ldmatrix.sync.aligned.m8n8.x4.shared.b16 {%0,%1,%2,%3}, [%4];"
                             : "=r"(a[mi][0]), "=r"(a[mi][1]), "=r"(a[mi][2]), "=r"(a[mi][3])
                             : "r"(addr));
            }
            // B fragments: 4 x ldmatrix.x4 covering 8 n-tiles (2 per x4)
#pragma unroll
            for (int np = 0; np < 4; np++) {
                uint32_t b[4];
                uint32_t addr = smem_u32(
                    &Bs[buf][wn + np * 16 + (tg >> 1) * 8 + tr][kb16 + (tg & 1) * 8]);
                asm volatile("ldmatrix.sync.aligned.m8n8.x4.shared.b16 {%0,%1,%2,%3}, [%4];"
                             : "=r"(b[0]), "=r"(b[1]), "=r"(b[2]), "=r"(b[3])
                             : "r"(addr));
#pragma unroll
                for (int mi = 0; mi < 2; mi++) {
#pragma unroll
                    for (int h = 0; h < 2; h++) {
                        float* c = acc[mi][np * 2 + h];
                        asm volatile(
                            "mma.sync.aligned.m16n8k16.row.col.f32.bf16.bf16.f32 "
                            "{%0,%1,%2,%3}, {%4,%5,%6,%7}, {%8,%9}, {%0,%1,%2,%3};"
                            : "+f"(c[0]), "+f"(c[1]), "+f"(c[2]), "+f"(c[3])
                            : "r"(a[mi][0]), "r"(a[mi][1]), "r"(a[mi][2]), "r"(a[mi][3]),
                              "r"(b[h * 2]), "r"(b[h * 2 + 1]));
                    }
                }
            }
        }
        __syncthreads();
    }

    // epilogue
#pragma unroll
    for (int mi = 0; mi < 2; mi++) {
        int r0 = m0 + wm + mi * 16 + (lane >> 2);
#pragma unroll
        for (int ni = 0; ni < 8; ni++) {
            int cc = n0 + wn + ni * 8 + (lane & 3) * 2;
            if (r0 < M)
                *(float2*)(C + (size_t)r0 * 256 + cc) = make_float2(acc[mi][ni][0], acc[mi][ni][1]);
            if (r0 + 8 < M)
                *(float2*)(C + (size_t)(r0 + 8) * 256 + cc) = make_float2(acc[mi][ni][2], acc[mi][ni][3]);
        }
    }
}

// ---------------- fp32 SGEMM (small MLP head only) ----------------
template <bool BIAS, bool RELU>
__global__ void __launch_bounds__(256)
sgemm_kernel(const float* __restrict__ A, const float* __restrict__ B,
             const float* __restrict__ bias, float* __restrict__ C,
             int M, int K, int N) {
    __shared__ float As[8][128];
    __shared__ float Bs[8][128];
    const int tid = threadIdx.x;
    const int m0 = blockIdx.y * 128;
    const int n0 = blockIdx.x * 128;

    const int arow = tid >> 1;
    const int acol = (tid & 1) * 4;
    const int bkrow = tid >> 5;
    const int bcol = (tid & 31) * 4;

    const int ty = tid >> 4;
    const int tx = tid & 15;

    float acc[8][8];
#pragma unroll
    for (int i = 0; i < 8; i++)
#pragma unroll
        for (int j = 0; j < 8; j++) acc[i][j] = 0.0f;

    for (int k0 = 0; k0 < K; k0 += 8) {
        float4 av = make_float4(0.f, 0.f, 0.f, 0.f);
        int gr = m0 + arow;
        if (gr < M) av = *(const float4*)(A + (size_t)gr * K + k0 + acol);
        As[acol + 0][arow] = av.x;
        As[acol + 1][arow] = av.y;
        As[acol + 2][arow] = av.z;
        As[acol + 3][arow] = av.w;
        float4 bv = *(const float4*)(B + (size_t)(k0 + bkrow) * N + n0 + bcol);
        *(float4*)&Bs[bkrow][bcol] = bv;
        __syncthreads();

#pragma unroll
        for (int kk = 0; kk < 8; kk++) {
            float ar[8], br[8];
            float4 a0 = *(const float4*)&As[kk][ty * 8];
            float4 a1 = *(const float4*)&As[kk][ty * 8 + 4];
            float4 b0 = *(const float4*)&Bs[kk][tx * 8];
            float4 b1 = *(const float4*)&Bs[kk][tx * 8 + 4];
            ar[0] = a0.x; ar[1] = a0.y; ar[2] = a0.z; ar[3] = a0.w;
            ar[4] = a1.x; ar[5] = a1.y; ar[6] = a1.z; ar[7] = a1.w;
            br[0] = b0.x; br[1] = b0.y; br[2] = b0.z; br[3] = b0.w;
            br[4] = b1.x; br[5] = b1.y; br[6] = b1.z; br[7] = b1.w;
#pragma unroll
            for (int i = 0; i < 8; i++)
#pragma unroll
                for (int j = 0; j < 8; j++)
                    acc[i][j] = fmaf(ar[i], br[j], acc[i][j]);
        }
        __syncthreads();
    }

#pragma unroll
    for (int i = 0; i < 8; i++) {
        int row = m0 + ty * 8 + i;
        if (row >= M) continue;
#pragma unroll
        for (int j = 0; j < 8; j++) {
            int colc = n0 + tx * 8 + j;
            float v = acc[i][j];
            if (BIAS) v += bias[colc];
            if (RELU) v = fmaxf(v, 0.0f);
            C[(size_t)row * N + colc] = v;
        }
    }
}

// ---------------- SpMM (CSR by dst) + self-loop + bias (+relu) ----------------
template <bool RELU>
__global__ void __launch_bounds__(256)
spmm_kernel(const float* __restrict__ Hin, const float* __restrict__ bias,
            float* __restrict__ Hout) {
    int node = blockIdx.x * 4 + (threadIdx.x >> 6);
    if (node >= NN) return;
    int lane = threadIdx.x & 63;
    float di = g_dinv[node];
    const float4* hp = (const float4*)Hin;

    float4 a = hp[(size_t)node * 64 + lane];
    float w0 = di * di;
    float4 acc = make_float4(a.x * w0, a.y * w0, a.z * w0, a.w * w0);

    int s = g_rowoff[node];
    int e = g_rowoff[node + 1];
    int p = s;
    for (; p + 2 <= e; p += 2) {
        int j0 = g_col[p], j1 = g_col[p + 1];
        float w0e = di * g_w[p], w1e = di * g_w[p + 1];
        float4 v0 = hp[(size_t)j0 * 64 + lane];
        float4 v1 = hp[(size_t)j1 * 64 + lane];
        acc.x = fmaf(w0e, v0.x, acc.x); acc.y = fmaf(w0e, v0.y, acc.y);
        acc.z = fmaf(w0e, v0.z, acc.z); acc.w = fmaf(w0e, v0.w, acc.w);
        acc.x = fmaf(w1e, v1.x, acc.x); acc.y = fmaf(w1e, v1.y, acc.y);
        acc.z = fmaf(w1e, v1.z, acc.z); acc.w = fmaf(w1e, v1.w, acc.w);
    }
    if (p < e) {
        int j0 = g_col[p];
        float w0e = di * g_w[p];
        float4 v0 = hp[(size_t)j0 * 64 + lane];
        acc.x = fmaf(w0e, v0.x, acc.x); acc.y = fmaf(w0e, v0.y, acc.y);
        acc.z = fmaf(w0e, v0.z, acc.z); acc.w = fmaf(w0e, v0.w, acc.w);
    }
    float4 b = ((const float4*)bias)[lane];
    acc.x += b.x; acc.y += b.y; acc.z += b.z; acc.w += b.w;
    if (RELU) {
        acc.x = fmaxf(acc.x, 0.f); acc.y = fmaxf(acc.y, 0.f);
        acc.z = fmaxf(acc.z, 0.f); acc.w = fmaxf(acc.w, 0.f);
    }
    ((float4*)Hout)[(size_t)node * 64 + lane] = acc;
}

// ---------------- pooling (batch is sorted) ----------------
__global__ void bounds_kernel(const int* __restrict__ batch) {
    int i = blockIdx.x * blockDim.x + threadIdx.x;
    if (i >= NN) return;
    int b = batch[i];
    int prev = (i == 0) ? -1 : batch[i - 1];
    for (int g = prev + 1; g <= b; g++) g_gstart[g] = i;
    if (i == NN - 1)
        for (int g = b + 1; g <= GG; g++) g_gstart[g] = NN;
}

__global__ void pool_kernel(const float* __restrict__ H) {
    int g = blockIdx.x;
    int c = threadIdx.x;
    int s = g_gstart[g];
    int e = g_gstart[g + 1];
    float acc = 0.0f;
    for (int i = s; i < e; i++) acc += H[(size_t)i * HD + c];
    float cnt = (float)(e - s);
    if (cnt < 1.0f) cnt = 1.0f;
    g_pooled[g * HD + c] = acc / cnt;
}

// ---------------- launch ----------------
extern "C" void kernel_launch(void* const* d_in, const int* in_sizes, int n_in,
                              void* d_out, int out_size) {
    const float* x     = (const float*)d_in[0];
    const int*   src   = (const int*)d_in[1];
    const int*   dst   = (const int*)d_in[2];
    const int*   batch = (const int*)d_in[3];
    const float* W1 = (const float*)d_in[4];
    const float* b1 = (const float*)d_in[5];
    const float* W2 = (const float*)d_in[6];
    const float* b2 = (const float*)d_in[7];
    const float* W3 = (const float*)d_in[8];
    const float* b3 = (const float*)d_in[9];
    const float* Wm1 = (const float*)d_in[10];
    const float* bm1 = (const float*)d_in[11];
    const float* Wm2 = (const float*)d_in[12];
    const float* bm2 = (const float*)d_in[13];
    float* out = (float*)d_out;

    float *t, *h, *pooled, *mlp1;
    __nv_bfloat16 *a3, *b3p;
    cudaGetSymbolAddress((void**)&t, g_t);
    cudaGetSymbolAddress((void**)&h, g_h);
    cudaGetSymbolAddress((void**)&pooled, g_pooled);
    cudaGetSymbolAddress((void**)&mlp1, g_mlp1);
    cudaGetSymbolAddress((void**)&a3, g_a3);
    cudaGetSymbolAddress((void**)&b3p, g_b3);

    const int TB = 256;
    const size_t BSTRIDE = (size_t)HD * 3 * HD;  // per-layer B3 block

    // ----- CSR + degrees -----
    zero_deg_kernel<<<(NN + TB - 1) / TB, TB>>>();
    count_kernel<<<(EE + TB - 1) / TB, TB>>>(dst);
    scan_kernel<<<1, 1024>>>();
    dinv_kernel<<<(NN + TB - 1) / TB, TB>>>();
    scatter_kernel<<<(EE + TB - 1) / TB, TB>>>(src, dst);

    // ----- weight splits -----
    splitW_kernel<<<(FIN * HD + TB - 1) / TB, TB>>>(W1, b3p + 0 * BSTRIDE, FIN, HD);
    splitW_kernel<<<(HD * HD + TB - 1) / TB, TB>>>(W2, b3p + 1 * BSTRIDE, HD, HD);
    splitW_kernel<<<(HD * HD + TB - 1) / TB, TB>>>(W3, b3p + 2 * BSTRIDE, HD, HD);

    dim3 gemm_grid(2, (NN + 127) / 128);   // N=256 -> 2 col blocks
    const int spmm_grid = (NN + 3) / 4;

    // ----- layer 1 -----
    splitA_kernel<<<(NN * FIN / 2 + TB - 1) / TB, TB>>>(x, a3, NN, FIN);
    gemm_mma_kernel<<<gemm_grid, 256>>>(a3, b3p + 0 * BSTRIDE, t, NN, 3 * FIN);
    spmm_kernel<true><<<spmm_grid, 256>>>(t, b1, h);
    // ----- layer 2 -----
    splitA_kernel<<<(NN * HD / 2 + TB - 1) / TB, TB>>>(h, a3, NN, HD);
    gemm_mma_kernel<<<gemm_grid, 256>>>(a3, b3p + 1 * BSTRIDE, t, NN, 3 * HD);
    spmm_kernel<true><<<spmm_grid, 256>>>(t, b2, h);
    // ----- layer 3 (no relu) -----
    splitA_kernel<<<(NN * HD / 2 + TB - 1) / TB, TB>>>(h, a3, NN, HD);
    gemm_mma_kernel<<<gemm_grid, 256>>>(a3, b3p + 2 * BSTRIDE, t, NN, 3 * HD);
    spmm_kernel<false><<<spmm_grid, 256>>>(t, b3, h);

    // ----- pooling -----
    bounds_kernel<<<(NN + TB - 1) / TB, TB>>>(batch);
    pool_kernel<<<GG, HD>>>(h);

    // ----- MLP head -----
    dim3 mlp1_grid(NHID_ / 128, (GG + 127) / 128);
    sgemm_kernel<true, true><<<mlp1_grid, 256>>>(pooled, Wm1, bm1, mlp1, GG, HD, NHID_);
    dim3 mlp2_grid(NOUT_ / 128, (GG + 127) / 128);
    sgemm_kernel<true, false><<<mlp2_grid, 256>>>(mlp1, Wm2, bm2, out, GG, NHID_, NOUT_);
}

// round 4
// speedup vs baseline: 1.7322x; 1.7322x over previous
#include <cuda_runtime.h>
#include <cuda_fp16.h>
#include <math.h>
#include <stdint.h>

#define NN   100000
#define EE   1600000
#define FIN  128
#define HD   256
#define NHID_ 512
#define NOUT_ 256
#define GG   256

__device__ __forceinline__ uint32_t smem_u32(const void* p) {
    uint32_t a;
    asm("{ .reg .u64 t; cvta.to.shared.u64 t, %1; cvt.u32.u64 %0, t; }" : "=r"(a) : "l"(p));
    return a;
}

// ---------------- scratch (no allocation allowed) ----------------
__device__ __align__(256) float g_t[(size_t)NN * HD];              // GEMM out / SpMM in
__device__ __align__(256) float g_h[(size_t)NN * HD];              // fp32 activations (layer3 / pooling)
__device__ __align__(256) __half g_a2[(size_t)NN * 2 * HD];        // packed [hi|lo] fp16 A
__device__ __align__(256) __half g_b2[3][HD * 2 * HD];             // packed [hi|hi] fp16 W^T
__device__ int   g_deg[NN];
__device__ float g_dinv[NN];
__device__ int   g_rowoff[NN + 1];
__device__ int   g_cursor[NN];
__device__ int   g_col[EE];
__device__ float g_w[EE];
__device__ int   g_gstart[GG + 1];
__device__ float g_pooled[GG * HD];
__device__ float g_mlp1[GG * NHID_];

// ---------------- CSR construction ----------------
__global__ void zero_deg_kernel() {
    int i = blockIdx.x * blockDim.x + threadIdx.x;
    if (i < NN) g_deg[i] = 0;
}

__global__ void count_kernel(const int* __restrict__ dst) {
    int e = blockIdx.x * blockDim.x + threadIdx.x;
    if (e < EE) atomicAdd(&g_deg[dst[e]], 1);
}

__global__ void scan_kernel() {
    __shared__ int sh[1024];
    __shared__ int carry;
    int tid = threadIdx.x;
    if (tid == 0) carry = 0;
    __syncthreads();
    for (int base = 0; base < NN; base += 1024) {
        int i = base + tid;
        int v = (i < NN) ? g_deg[i] : 0;
        sh[tid] = v;
        __syncthreads();
        for (int off = 1; off < 1024; off <<= 1) {
            int t = (tid >= off) ? sh[tid - off] : 0;
            __syncthreads();
            sh[tid] += t;
            __syncthreads();
        }
        int excl = carry + sh[tid] - v;
        if (i < NN) { g_rowoff[i] = excl; g_cursor[i] = excl; }
        __syncthreads();
        if (tid == 1023) carry += sh[1023];
        __syncthreads();
    }
    if (tid == 0) g_rowoff[NN] = carry;
}

__global__ void dinv_kernel() {
    int i = blockIdx.x * blockDim.x + threadIdx.x;
    if (i < NN) g_dinv[i] = rsqrtf(1.0f + (float)g_deg[i]);
}

__global__ void scatter_kernel(const int* __restrict__ src, const int* __restrict__ dst) {
    int e = blockIdx.x * blockDim.x + threadIdx.x;
    if (e < EE) {
        int s = src[e];
        int p = atomicAdd(&g_cursor[dst[e]], 1);
        g_col[p] = s;
        g_w[p] = g_dinv[s];
    }
}

// ---------------- splits ----------------
// x [M,K] fp32 -> A2 [M,2K] fp16: [hi | lo]
__global__ void splitX_kernel(const float* __restrict__ A,
                              __half* __restrict__ A2, int M, int K) {
    int idx = blockIdx.x * blockDim.x + threadIdx.x;
    int half_ = K >> 1;
    if (idx >= M * half_) return;
    int m = idx / half_;
    int kk = (idx - m * half_) * 2;
    float2 a = *(const float2*)(A + (size_t)m * K + kk);
    __half hx = __float2half_rn(a.x);
    __half hy = __float2half_rn(a.y);
    __half2 hp; hp.x = hx; hp.y = hy;
    __half2 lp;
    lp.x = __float2half_rn(a.x - __half2float(hx));
    lp.y = __float2half_rn(a.y - __half2float(hy));
    __half* row = A2 + (size_t)m * (2 * K);
    *(__half2*)(row + kk)     = hp;
    *(__half2*)(row + K + kk) = lp;
}

// W [K,N] fp32 -> B2 [N,2K] fp16 rows: [hi | hi] (transposed)
__global__ void splitW_kernel(const float* __restrict__ W,
                              __half* __restrict__ B2, int K, int N) {
    int idx = blockIdx.x * blockDim.x + threadIdx.x;
    if (idx >= K * N) return;
    int k = idx / N, n = idx % N;
    __half hi = __float2half_rn(W[idx]);
    __half* row = B2 + (size_t)n * (2 * K);
    row[k]     = hi;
    row[K + k] = hi;
}

// ---------------- fp16 mma.sync GEMM: C[M,256] = A2[M,K2] @ B2[256,K2]^T ----------------
// BM=128, BN=256 (full), BK=32, 512 threads (16 warps, warp tile 32x64), 3-stage cp.async.
#define STAGE_BYTES 30720   // A: 128*40*2 = 10240 ; B: 256*40*2 = 20480
__global__ void __launch_bounds__(512, 1)
gemm_mma2_kernel(const __half* __restrict__ A2,
                 const __half* __restrict__ B2,
                 float* __restrict__ C, int M, int K2)
{
    extern __shared__ char smem_raw[];
    const uint32_t base = smem_u32(smem_raw);

    const int tid  = threadIdx.x;
    const int wid  = tid >> 5;
    const int lane = tid & 31;
    const int m0 = blockIdx.x * 128;
    const int wm = (wid & 3) * 32;     // 0..96
    const int wn = (wid >> 2) * 64;    // 0..192

    float acc[2][8][4];
#pragma unroll
    for (int i = 0; i < 2; i++)
#pragma unroll
        for (int j = 0; j < 8; j++)
#pragma unroll
            for (int q = 0; q < 4; q++) acc[i][j][q] = 0.0f;

    const int NKB = K2 / 32;

    auto load_stage = [&](int kb, int s) {
        const uint32_t sb = base + (uint32_t)s * STAGE_BYTES;
        int k0 = kb * 32;
        {   // A: 512 x 16B
            int row = tid >> 2, seg = tid & 3;
            const __half* gp = A2 + (size_t)(m0 + row) * K2 + k0 + seg * 8;
            uint32_t d = sb + row * 80 + seg * 16;
            uint32_t sz = (m0 + row < M) ? 16u : 0u;
            asm volatile("cp.async.cg.shared.global [%0], [%1], 16, %2;"
                         :: "r"(d), "l"(gp), "r"(sz) : "memory");
        }
#pragma unroll
        for (int it = 0; it < 2; it++) {   // B: 1024 x 16B
            int u = tid + it * 512;
            int row = u >> 2, seg = u & 3;
            const __half* gp = B2 + (size_t)row * K2 + k0 + seg * 8;
            uint32_t d = sb + 10240 + row * 80 + seg * 16;
            asm volatile("cp.async.cg.shared.global [%0], [%1], 16;"
                         :: "r"(d), "l"(gp) : "memory");
        }
        asm volatile("cp.async.commit_group;" ::: "memory");
    };

    load_stage(0, 0);
    load_stage(1, 1);

    const int tg = lane >> 3;   // 0..3
    const int tr = lane & 7;    // 0..7

    for (int kb = 0; kb < NKB; kb++) {
        int s = kb % 3;
        if (kb + 2 < NKB) {
            load_stage(kb + 2, (kb + 2) % 3);
            asm volatile("cp.async.wait_group 2;" ::: "memory");
        } else if (kb + 1 < NKB) {
            asm volatile("cp.async.wait_group 1;" ::: "memory");
        } else {
            asm volatile("cp.async.wait_group 0;" ::: "memory");
        }
        __syncthreads();

        const uint32_t Ab = base + (uint32_t)s * STAGE_BYTES;
        const uint32_t Bb = Ab + 10240;

#pragma unroll
        for (int ks = 0; ks < 2; ks++) {
            int kb16 = ks * 16;
            uint32_t a[2][4];
#pragma unroll
            for (int mi = 0; mi < 2; mi++) {
                uint32_t addr = Ab + (wm + mi * 16 + tr + (tg & 1) * 8) * 80
                                   + (kb16 + (tg >> 1) * 8) * 2;
                asm volatile("ldmatrix.sync.aligned.m8n8.x4.shared.b16 {%0,%1,%2,%3}, [%4];"
                             : "=r"(a[mi][0]), "=r"(a[mi][1]), "=r"(a[mi][2]), "=r"(a[mi][3])
                             : "r"(addr));
            }
#pragma unroll
            for (int np = 0; np < 4; np++) {
                uint32_t b[4];
                uint32_t addr = Bb + (wn + np * 16 + (tg >> 1) * 8 + tr) * 80
                                   + (kb16 + (tg & 1) * 8) * 2;
                asm volatile("ldmatrix.sync.aligned.m8n8.x4.shared.b16 {%0,%1,%2,%3}, [%4];"
                             : "=r"(b[0]), "=r"(b[1]), "=r"(b[2]), "=r"(b[3])
                             : "r"(addr));
#pragma unroll
                for (int mi = 0; mi < 2; mi++) {
#pragma unroll
                    for (int hh = 0; hh < 2; hh++) {
                        float* c = acc[mi][np * 2 + hh];
                        asm volatile(
                            "mma.sync.aligned.m16n8k16.row.col.f32.f16.f16.f32 "
                            "{%0,%1,%2,%3}, {%4,%5,%6,%7}, {%8,%9}, {%0,%1,%2,%3};"
                            : "+f"(c[0]), "+f"(c[1]), "+f"(c[2]), "+f"(c[3])
                            : "r"(a[mi][0]), "r"(a[mi][1]), "r"(a[mi][2]), "r"(a[mi][3]),
                              "r"(b[hh * 2]), "r"(b[hh * 2 + 1]));
                    }
                }
            }
        }
        __syncthreads();
    }

    // epilogue
#pragma unroll
    for (int mi = 0; mi < 2; mi++) {
        int r0 = m0 + wm + mi * 16 + (lane >> 2);
#pragma unroll
        for (int ni = 0; ni < 8; ni++) {
            int cc = wn + ni * 8 + (lane & 3) * 2;
            if (r0 < M)
                *(float2*)(C + (size_t)r0 * 256 + cc) = make_float2(acc[mi][ni][0], acc[mi][ni][1]);
            if (r0 + 8 < M)
                *(float2*)(C + (size_t)(r0 + 8) * 256 + cc) = make_float2(acc[mi][ni][2], acc[mi][ni][3]);
        }
    }
}

// ---------------- fp32 SGEMM (small MLP head only) ----------------
template <bool BIAS, bool RELU>
__global__ void __launch_bounds__(256)
sgemm_kernel(const float* __restrict__ A, const float* __restrict__ B,
             const float* __restrict__ bias, float* __restrict__ C,
             int M, int K, int N) {
    __shared__ float As[8][128];
    __shared__ float Bs[8][128];
    const int tid = threadIdx.x;
    const int m0 = blockIdx.y * 128;
    const int n0 = blockIdx.x * 128;

    const int arow = tid >> 1;
    const int acol = (tid & 1) * 4;
    const int bkrow = tid >> 5;
    const int bcol = (tid & 31) * 4;

    const int ty = tid >> 4;
    const int tx = tid & 15;

    float acc[8][8];
#pragma unroll
    for (int i = 0; i < 8; i++)
#pragma unroll
        for (int j = 0; j < 8; j++) acc[i][j] = 0.0f;

    for (int k0 = 0; k0 < K; k0 += 8) {
        float4 av = make_float4(0.f, 0.f, 0.f, 0.f);
        int gr = m0 + arow;
        if (gr < M) av = *(const float4*)(A + (size_t)gr * K + k0 + acol);
        As[acol + 0][arow] = av.x;
        As[acol + 1][arow] = av.y;
        As[acol + 2][arow] = av.z;
        As[acol + 3][arow] = av.w;
        float4 bv = *(const float4*)(B + (size_t)(k0 + bkrow) * N + n0 + bcol);
        *(float4*)&Bs[bkrow][bcol] = bv;
        __syncthreads();

#pragma unroll
        for (int kk = 0; kk < 8; kk++) {
            float ar[8], br[8];
            float4 a0 = *(const float4*)&As[kk][ty * 8];
            float4 a1 = *(const float4*)&As[kk][ty * 8 + 4];
            float4 b0 = *(const float4*)&Bs[kk][tx * 8];
            float4 b1 = *(const float4*)&Bs[kk][tx * 8 + 4];
            ar[0] = a0.x; ar[1] = a0.y; ar[2] = a0.z; ar[3] = a0.w;
            ar[4] = a1.x; ar[5] = a1.y; ar[6] = a1.z; ar[7] = a1.w;
            br[0] = b0.x; br[1] = b0.y; br[2] = b0.z; br[3] = b0.w;
            br[4] = b1.x; br[5] = b1.y; br[6] = b1.z; br[7] = b1.w;
#pragma unroll
            for (int i = 0; i < 8; i++)
#pragma unroll
                for (int j = 0; j < 8; j++)
                    acc[i][j] = fmaf(ar[i], br[j], acc[i][j]);
        }
        __syncthreads();
    }

#pragma unroll
    for (int i = 0; i < 8; i++) {
        int row = m0 + ty * 8 + i;
        if (row >= M) continue;
#pragma unroll
        for (int j = 0; j < 8; j++) {
            int colc = n0 + tx * 8 + j;
            float v = acc[i][j];
            if (BIAS) v += bias[colc];
            if (RELU) v = fmaxf(v, 0.0f);
            C[(size_t)row * N + colc] = v;
        }
    }
}

// ---------------- SpMM (CSR by dst) + self-loop + bias (+relu) ----------------
// PACK: emit fp16 [hi|lo] packed row (for next GEMM). else emit fp32 row.
template <bool RELU, bool PACK>
__global__ void __launch_bounds__(256)
spmm_kernel(const float* __restrict__ Hin, const float* __restrict__ bias,
            float* __restrict__ HoutF, __half* __restrict__ HoutH) {
    int node = blockIdx.x * 4 + (threadIdx.x >> 6);
    if (node >= NN) return;
    int lane = threadIdx.x & 63;
    float di = g_dinv[node];
    const float4* hp = (const float4*)Hin;

    float4 a = hp[(size_t)node * 64 + lane];
    float w0 = di * di;
    float4 acc = make_float4(a.x * w0, a.y * w0, a.z * w0, a.w * w0);

    int s = g_rowoff[node];
    int e = g_rowoff[node + 1];
    int p = s;
    for (; p + 2 <= e; p += 2) {
        int j0 = g_col[p], j1 = g_col[p + 1];
        float w0e = di * g_w[p], w1e = di * g_w[p + 1];
        float4 v0 = hp[(size_t)j0 * 64 + lane];
        float4 v1 = hp[(size_t)j1 * 64 + lane];
        acc.x = fmaf(w0e, v0.x, acc.x); acc.y = fmaf(w0e, v0.y, acc.y);
        acc.z = fmaf(w0e, v0.z, acc.z); acc.w = fmaf(w0e, v0.w, acc.w);
        acc.x = fmaf(w1e, v1.x, acc.x); acc.y = fmaf(w1e, v1.y, acc.y);
        acc.z = fmaf(w1e, v1.z, acc.z); acc.w = fmaf(w1e, v1.w, acc.w);
    }
    if (p < e) {
        int j0 = g_col[p];
        float w0e = di * g_w[p];
        float4 v0 = hp[(size_t)j0 * 64 + lane];
        acc.x = fmaf(w0e, v0.x, acc.x); acc.y = fmaf(w0e, v0.y, acc.y);
        acc.z = fmaf(w0e, v0.z, acc.z); acc.w = fmaf(w0e, v0.w, acc.w);
    }
    float4 b = ((const float4*)bias)[lane];
    acc.x += b.x; acc.y += b.y; acc.z += b.z; acc.w += b.w;
    if (RELU) {
        acc.x = fmaxf(acc.x, 0.f); acc.y = fmaxf(acc.y, 0.f);
        acc.z = fmaxf(acc.z, 0.f); acc.w = fmaxf(acc.w, 0.f);
    }
    if (PACK) {
        __half hx = __float2half_rn(acc.x);
        __half hy = __float2half_rn(acc.y);
        __half hz = __float2half_rn(acc.z);
        __half hw = __float2half_rn(acc.w);
        __half2 hi0; hi0.x = hx; hi0.y = hy;
        __half2 hi1; hi1.x = hz; hi1.y = hw;
        __half2 lo0, lo1;
        lo0.x = __float2half_rn(acc.x - __half2float(hx));
        lo0.y = __float2half_rn(acc.y - __half2float(hy));
        lo1.x = __float2half_rn(acc.z - __half2float(hz));
        lo1.y = __float2half_rn(acc.w - __half2float(hw));
        __half* row = HoutH + (size_t)node * 512;
        *(__half2*)(row + 4 * lane)       = hi0;
        *(__half2*)(row + 4 * lane + 2)   = hi1;
        *(__half2*)(row + 256 + 4 * lane)     = lo0;
        *(__half2*)(row + 256 + 4 * lane + 2) = lo1;
    } else {
        ((float4*)HoutF)[(size_t)node * 64 + lane] = acc;
    }
}

// ---------------- pooling (batch is sorted) ----------------
__global__ void bounds_kernel(const int* __restrict__ batch) {
    int i = blockIdx.x * blockDim.x + threadIdx.x;
    if (i >= NN) return;
    int b = batch[i];
    int prev = (i == 0) ? -1 : batch[i - 1];
    for (int g = prev + 1; g <= b; g++) g_gstart[g] = i;
    if (i == NN - 1)
        for (int g = b + 1; g <= GG; g++) g_gstart[g] = NN;
}

__global__ void pool_kernel(const float* __restrict__ H) {
    int g = blockIdx.x;
    int c = threadIdx.x;
    int s = g_gstart[g];
    int e = g_gstart[g + 1];
    float acc = 0.0f;
    for (int i = s; i < e; i++) acc += H[(size_t)i * HD + c];
    float cnt = (float)(e - s);
    if (cnt < 1.0f) cnt = 1.0f;
    g_pooled[g * HD + c] = acc / cnt;
}

// ---------------- launch ----------------
extern "C" void kernel_launch(void* const* d_in, const int* in_sizes, int n_in,
                              void* d_out, int out_size) {
    const float* x     = (const float*)d_in[0];
    const int*   src   = (const int*)d_in[1];
    const int*   dst   = (const int*)d_in[2];
    const int*   batch = (const int*)d_in[3];
    const float* W1 = (const float*)d_in[4];
    const float* b1 = (const float*)d_in[5];
    const float* W2 = (const float*)d_in[6];
    const float* b2 = (const float*)d_in[7];
    const float* W3 = (const float*)d_in[8];
    const float* b3 = (const float*)d_in[9];
    const float* Wm1 = (const float*)d_in[10];
    const float* bm1 = (const float*)d_in[11];
    const float* Wm2 = (const float*)d_in[12];
    const float* bm2 = (const float*)d_in[13];
    float* out = (float*)d_out;

    float *t, *h, *pooled, *mlp1;
    __half *a2, *b2p;
    cudaGetSymbolAddress((void**)&t, g_t);
    cudaGetSymbolAddress((void**)&h, g_h);
    cudaGetSymbolAddress((void**)&pooled, g_pooled);
    cudaGetSymbolAddress((void**)&mlp1, g_mlp1);
    cudaGetSymbolAddress((void**)&a2, g_a2);
    cudaGetSymbolAddress((void**)&b2p, g_b2);

    const int GSMEM = 3 * STAGE_BYTES;   // 92160
    cudaFuncSetAttribute(gemm_mma2_kernel,
                         cudaFuncAttributeMaxDynamicSharedMemorySize, GSMEM);

    const int TB = 256;
    const size_t BSTRIDE = (size_t)HD * 2 * HD;  // per-layer B2 block (max size)

    const int gemm_grid = (NN + 127) / 128;   // 782
    const int spmm_grid = (NN + 3) / 4;

    // --- front-load GEMM path so ncu's skip-N capture lands on gemm (4th launch) ---
    splitW_kernel<<<(FIN * HD + TB - 1) / TB, TB>>>(W1, b2p + 0 * BSTRIDE, FIN, HD);   // 1
    splitW_kernel<<<(HD * HD + TB - 1) / TB, TB>>>(W2, b2p + 1 * BSTRIDE, HD, HD);     // 2
    splitX_kernel<<<(NN * FIN / 2 + TB - 1) / TB, TB>>>(x, a2, NN, FIN);               // 3
    gemm_mma2_kernel<<<gemm_grid, 512, GSMEM>>>(a2, b2p + 0 * BSTRIDE, t, NN, 2 * FIN); // 4 (profiled)
    splitW_kernel<<<(HD * HD + TB - 1) / TB, TB>>>(W3, b2p + 2 * BSTRIDE, HD, HD);     // 5

    // ----- CSR + degrees -----
    zero_deg_kernel<<<(NN + TB - 1) / TB, TB>>>();
    count_kernel<<<(EE + TB - 1) / TB, TB>>>(dst);
    scan_kernel<<<1, 1024>>>();
    dinv_kernel<<<(NN + TB - 1) / TB, TB>>>();
    scatter_kernel<<<(EE + TB - 1) / TB, TB>>>(src, dst);

    // ----- layer 1 aggregation (emit packed fp16) -----
    spmm_kernel<true, true><<<spmm_grid, 256>>>(t, b1, nullptr, a2);
    // ----- layer 2 -----
    gemm_mma2_kernel<<<gemm_grid, 512, GSMEM>>>(a2, b2p + 1 * BSTRIDE, t, NN, 2 * HD);
    spmm_kernel<true, true><<<spmm_grid, 256>>>(t, b2, nullptr, a2);
    // ----- layer 3 (no relu; emit fp32 for pooling) -----
    gemm_mma2_kernel<<<gemm_grid, 512, GSMEM>>>(a2, b2p + 2 * BSTRIDE, t, NN, 2 * HD);
    spmm_kernel<false, false><<<spmm_grid, 256>>>(t, b3, h, nullptr);

    // ----- pooling -----
    bounds_kernel<<<(NN + TB - 1) / TB, TB>>>(batch);
    pool_kernel<<<GG, HD>>>(h);

    // ----- MLP head -----
    dim3 mlp1_grid(NHID_ / 128, (GG + 127) / 128);
    sgemm_kernel<true, true><<<mlp1_grid, 256>>>(pooled, Wm1, bm1, mlp1, GG, HD, NHID_);
    dim3 mlp2_grid(NOUT_ / 128, (GG + 127) / 128);
    sgemm_kernel<true, false><<<mlp2_grid, 256>>>(mlp1, Wm2, bm2, out, GG, NHID_, NOUT_);
}

// round 6
// speedup vs baseline: 1.9768x; 1.1412x over previous
#include <cuda_runtime.h>
#include <cuda_fp16.h>
#include <math.h>
#include <stdint.h>

#define NN   100000
#define EE   1600000
#define FIN  128
#define HD   256
#define NHID_ 512
#define NOUT_ 256
#define GG   256

__device__ __forceinline__ uint32_t smem_u32(const void* p) {
    uint32_t a;
    asm("{ .reg .u64 t; cvta.to.shared.u64 t, %1; cvt.u32.u64 %0, t; }" : "=r"(a) : "l"(p));
    return a;
}

// ---------------- scratch (no allocation allowed) ----------------
__device__ __align__(256) __half g_t16[(size_t)NN * HD];           // GEMM out (fp16) / SpMM in
__device__ __align__(256) float g_h[(size_t)NN * HD];              // fp32 activations (layer3 / pooling)
__device__ __align__(256) __half g_a2[(size_t)NN * 2 * HD];        // packed [hi|lo] fp16 A
__device__ __align__(256) __half g_b2[3][HD * 2 * HD];             // packed [hi|hi] fp16 W^T
__device__ int   g_deg[NN];
__device__ float g_dinv[NN];
__device__ int   g_rowoff[NN + 1];
__device__ int   g_cursor[NN];
__device__ int   g_col[EE];
__device__ float g_w[EE];
__device__ int   g_gstart[GG + 1];
__device__ float g_pooled[GG * HD];
__device__ float g_mlp1[GG * NHID_];

// ---------------- CSR construction ----------------
__global__ void zero_deg_kernel() {
    int i = blockIdx.x * blockDim.x + threadIdx.x;
    if (i < NN) g_deg[i] = 0;
}

__global__ void count_kernel(const int* __restrict__ dst) {
    int e = blockIdx.x * blockDim.x + threadIdx.x;
    if (e < EE) atomicAdd(&g_deg[dst[e]], 1);
}

__global__ void scan_kernel() {
    __shared__ int sh[1024];
    __shared__ int carry;
    int tid = threadIdx.x;
    if (tid == 0) carry = 0;
    __syncthreads();
    for (int base = 0; base < NN; base += 1024) {
        int i = base + tid;
        int v = (i < NN) ? g_deg[i] : 0;
        sh[tid] = v;
        __syncthreads();
        for (int off = 1; off < 1024; off <<= 1) {
            int t = (tid >= off) ? sh[tid - off] : 0;
            __syncthreads();
            sh[tid] += t;
            __syncthreads();
        }
        int excl = carry + sh[tid] - v;
        if (i < NN) { g_rowoff[i] = excl; g_cursor[i] = excl; }
        __syncthreads();
        if (tid == 1023) carry += sh[1023];
        __syncthreads();
    }
    if (tid == 0) g_rowoff[NN] = carry;
}

__global__ void dinv_kernel() {
    int i = blockIdx.x * blockDim.x + threadIdx.x;
    if (i < NN) g_dinv[i] = rsqrtf(1.0f + (float)g_deg[i]);
}

__global__ void scatter_kernel(const int* __restrict__ src, const int* __restrict__ dst) {
    int e = blockIdx.x * blockDim.x + threadIdx.x;
    if (e < EE) {
        int s = src[e];
        int p = atomicAdd(&g_cursor[dst[e]], 1);
        g_col[p] = s;
        g_w[p] = g_dinv[s];
    }
}

// ---------------- splits ----------------
// x [M,K] fp32 -> A2 [M,2K] fp16: [hi | lo]
__global__ void splitX_kernel(const float* __restrict__ A,
                              __half* __restrict__ A2, int M, int K) {
    int idx = blockIdx.x * blockDim.x + threadIdx.x;
    int half_ = K >> 1;
    if (idx >= M * half_) return;
    int m = idx / half_;
    int kk = (idx - m * half_) * 2;
    float2 a = *(const float2*)(A + (size_t)m * K + kk);
    __half hx = __float2half_rn(a.x);
    __half hy = __float2half_rn(a.y);
    __half2 hp; hp.x = hx; hp.y = hy;
    __half2 lp;
    lp.x = __float2half_rn(a.x - __half2float(hx));
    lp.y = __float2half_rn(a.y - __half2float(hy));
    __half* row = A2 + (size_t)m * (2 * K);
    *(__half2*)(row + kk)     = hp;
    *(__half2*)(row + K + kk) = lp;
}

// W [K,N] fp32 -> B2 [N,2K] fp16 rows: [hi | hi] (transposed)
__global__ void splitW_kernel(const float* __restrict__ W,
                              __half* __restrict__ B2, int K, int N) {
    int idx = blockIdx.x * blockDim.x + threadIdx.x;
    if (idx >= K * N) return;
    int k = idx / N, n = idx % N;
    __half hi = __float2half_rn(W[idx]);
    __half* row = B2 + (size_t)n * (2 * K);
    row[k]     = hi;
    row[K + k] = hi;
}

// ---------------- fp16 mma.sync GEMM: C16[M,256] = A2[M,K2] @ B2[256,K2]^T ----------------
// BM=128, BN=256 (full), BK=32, 512 threads (16 warps, warp tile 32x64), 3-stage cp.async.
#define STAGE_BYTES 30720   // A: 128*40*2 = 10240 ; B: 256*40*2 = 20480
__global__ void __launch_bounds__(512, 1)
gemm_mma2_kernel(const __half* __restrict__ A2,
                 const __half* __restrict__ B2,
                 __half* __restrict__ C16, int M, int K2)
{
    extern __shared__ char smem_raw[];
    const uint32_t base = smem_u32(smem_raw);

    const int tid  = threadIdx.x;
    const int wid  = tid >> 5;
    const int lane = tid & 31;
    const int m0 = blockIdx.x * 128;
    const int wm = (wid & 3) * 32;     // 0..96
    const int wn = (wid >> 2) * 64;    // 0..192

    float acc[2][8][4];
#pragma unroll
    for (int i = 0; i < 2; i++)
#pragma unroll
        for (int j = 0; j < 8; j++)
#pragma unroll
            for (int q = 0; q < 4; q++) acc[i][j][q] = 0.0f;

    const int NKB = K2 / 32;

    auto load_stage = [&](int kb, int s) {
        const uint32_t sb = base + (uint32_t)s * STAGE_BYTES;
        int k0 = kb * 32;
        {   // A: 512 x 16B
            int row = tid >> 2, seg = tid & 3;
            const __half* gp = A2 + (size_t)(m0 + row) * K2 + k0 + seg * 8;
            uint32_t d = sb + row * 80 + seg * 16;
            uint32_t sz = (m0 + row < M) ? 16u : 0u;
            asm volatile("cp.async.cg.shared.global [%0], [%1], 16, %2;"
                         :: "r"(d), "l"(gp), "r"(sz) : "memory");
        }
#pragma unroll
        for (int it = 0; it < 2; it++) {   // B: 1024 x 16B
            int u = tid + it * 512;
            int row = u >> 2, seg = u & 3;
            const __half* gp = B2 + (size_t)row * K2 + k0 + seg * 8;
            uint32_t d = sb + 10240 + row * 80 + seg * 16;
            asm volatile("cp.async.cg.shared.global [%0], [%1], 16;"
                         :: "r"(d), "l"(gp) : "memory");
        }
        asm volatile("cp.async.commit_group;" ::: "memory");
    };

    load_stage(0, 0);
    load_stage(1, 1);

    const int tg = lane >> 3;   // 0..3
    const int tr = lane & 7;    // 0..7

    for (int kb = 0; kb < NKB; kb++) {
        int s = kb % 3;
        if (kb + 2 < NKB) {
            load_stage(kb + 2, (kb + 2) % 3);
            asm volatile("cp.async.wait_group 2;" ::: "memory");
        } else if (kb + 1 < NKB) {
            asm volatile("cp.async.wait_group 1;" ::: "memory");
        } else {
            asm volatile("cp.async.wait_group 0;" ::: "memory");
        }
        __syncthreads();

        const uint32_t Ab = base + (uint32_t)s * STAGE_BYTES;
        const uint32_t Bb = Ab + 10240;

#pragma unroll
        for (int ks = 0; ks < 2; ks++) {
            int kb16 = ks * 16;
            uint32_t a[2][4];
#pragma unroll
            for (int mi = 0; mi < 2; mi++) {
                uint32_t addr = Ab + (wm + mi * 16 + tr + (tg & 1) * 8) * 80
                                   + (kb16 + (tg >> 1) * 8) * 2;
                asm volatile("ldmatrix.sync.aligned.m8n8.x4.shared.b16 {%0,%1,%2,%3}, [%4];"
                             : "=r"(a[mi][0]), "=r"(a[mi][1]), "=r"(a[mi][2]), "=r"(a[mi][3])
                             : "r"(addr));
            }
#pragma unroll
            for (int np = 0; np < 4; np++) {
                uint32_t b[4];
                uint32_t addr = Bb + (wn + np * 16 + (tg >> 1) * 8 + tr) * 80
                                   + (kb16 + (tg & 1) * 8) * 2;
                asm volatile("ldmatrix.sync.aligned.m8n8.x4.shared.b16 {%0,%1,%2,%3}, [%4];"
                             : "=r"(b[0]), "=r"(b[1]), "=r"(b[2]), "=r"(b[3])
                             : "r"(addr));
#pragma unroll
                for (int mi = 0; mi < 2; mi++) {
#pragma unroll
                    for (int hh = 0; hh < 2; hh++) {
                        float* c = acc[mi][np * 2 + hh];
                        asm volatile(
                            "mma.sync.aligned.m16n8k16.row.col.f32.f16.f16.f32 "
                            "{%0,%1,%2,%3}, {%4,%5,%6,%7}, {%8,%9}, {%0,%1,%2,%3};"
                            : "+f"(c[0]), "+f"(c[1]), "+f"(c[2]), "+f"(c[3])
                            : "r"(a[mi][0]), "r"(a[mi][1]), "r"(a[mi][2]), "r"(a[mi][3]),
                              "r"(b[hh * 2]), "r"(b[hh * 2 + 1]));
                    }
                }
            }
        }
        __syncthreads();
    }

    // epilogue: fp16 output
#pragma unroll
    for (int mi = 0; mi < 2; mi++) {
        int r0 = m0 + wm + mi * 16 + (lane >> 2);
#pragma unroll
        for (int ni = 0; ni < 8; ni++) {
            int cc = wn + ni * 8 + (lane & 3) * 2;
            float* c = acc[mi][ni];
            if (r0 < M) {
                __half2 v; v.x = __float2half_rn(c[0]); v.y = __float2half_rn(c[1]);
                *(__half2*)(C16 + (size_t)r0 * 256 + cc) = v;
            }
            if (r0 + 8 < M) {
                __half2 v; v.x = __float2half_rn(c[2]); v.y = __float2half_rn(c[3]);
                *(__half2*)(C16 + (size_t)(r0 + 8) * 256 + cc) = v;
            }
        }
    }
}

// ---------------- fp32 SGEMM (small MLP head only) ----------------
template <bool BIAS, bool RELU>
__global__ void __launch_bounds__(256)
sgemm_kernel(const float* __restrict__ A, const float* __restrict__ B,
             const float* __restrict__ bias, float* __restrict__ C,
             int M, int K, int N) {
    __shared__ float As[8][128];
    __shared__ float Bs[8][128];
    const int tid = threadIdx.x;
    const int m0 = blockIdx.y * 128;
    const int n0 = blockIdx.x * 128;

    const int arow = tid >> 1;
    const int acol = (tid & 1) * 4;
    const int bkrow = tid >> 5;
    const int bcol = (tid & 31) * 4;

    const int ty = tid >> 4;
    const int tx = tid & 15;

    float acc[8][8];
#pragma unroll
    for (int i = 0; i < 8; i++)
#pragma unroll
        for (int j = 0; j < 8; j++) acc[i][j] = 0.0f;

    for (int k0 = 0; k0 < K; k0 += 8) {
        float4 av = make_float4(0.f, 0.f, 0.f, 0.f);
        int gr = m0 + arow;
        if (gr < M) av = *(const float4*)(A + (size_t)gr * K + k0 + acol);
        As[acol + 0][arow] = av.x;
        As[acol + 1][arow] = av.y;
        As[acol + 2][arow] = av.z;
        As[acol + 3][arow] = av.w;
        float4 bv = *(const float4*)(B + (size_t)(k0 + bkrow) * N + n0 + bcol);
        *(float4*)&Bs[bkrow][bcol] = bv;
        __syncthreads();

#pragma unroll
        for (int kk = 0; kk < 8; kk++) {
            float ar[8], br[8];
            float4 a0 = *(const float4*)&As[kk][ty * 8];
            float4 a1 = *(const float4*)&As[kk][ty * 8 + 4];
            float4 b0 = *(const float4*)&Bs[kk][tx * 8];
            float4 b1 = *(const float4*)&Bs[kk][tx * 8 + 4];
            ar[0] = a0.x; ar[1] = a0.y; ar[2] = a0.z; ar[3] = a0.w;
            ar[4] = a1.x; ar[5] = a1.y; ar[6] = a1.z; ar[7] = a1.w;
            br[0] = b0.x; br[1] = b0.y; br[2] = b0.z; br[3] = b0.w;
            br[4] = b1.x; br[5] = b1.y; br[6] = b1.z; br[7] = b1.w;
#pragma unroll
            for (int i = 0; i < 8; i++)
#pragma unroll
                for (int j = 0; j < 8; j++)
                    acc[i][j] = fmaf(ar[i], br[j], acc[i][j]);
        }
        __syncthreads();
    }

#pragma unroll
    for (int i = 0; i < 8; i++) {
        int row = m0 + ty * 8 + i;
        if (row >= M) continue;
#pragma unroll
        for (int j = 0; j < 8; j++) {
            int colc = n0 + tx * 8 + j;
            float v = acc[i][j];
            if (BIAS) v += bias[colc];
            if (RELU) v = fmaxf(v, 0.0f);
            C[(size_t)row * N + colc] = v;
        }
    }
}

// ---------------- SpMM over fp16 rows + self-loop + bias (+relu) ----------------
// 4 nodes per 256-thread block; 64 lanes per node, each lane owns 4 channels (uint2).
// PACK: emit fp16 [hi|lo] packed row; else emit fp32 row.
template <bool RELU, bool PACK>
__global__ void __launch_bounds__(256)
spmm16_kernel(const __half* __restrict__ Hin, const float* __restrict__ bias,
              float* __restrict__ HoutF, __half* __restrict__ HoutH) {
    int node = blockIdx.x * 4 + (threadIdx.x >> 6);
    if (node >= NN) return;
    int lane = threadIdx.x & 63;
    float di = g_dinv[node];
    const uint2* hp2 = (const uint2*)Hin;  // 4 halves per uint2; 64 uint2 per 256-wide row

    float acc0, acc1, acc2, acc3;
    {
        float w0 = di * di;
        uint2 v = hp2[(size_t)node * 64 + lane];
        float2 f0 = __half22float2(*(__half2*)&v.x);
        float2 f1 = __half22float2(*(__half2*)&v.y);
        acc0 = f0.x * w0; acc1 = f0.y * w0;
        acc2 = f1.x * w0; acc3 = f1.y * w0;
    }

    int s = g_rowoff[node];
    int e = g_rowoff[node + 1];
    int p = s;
    for (; p + 2 <= e; p += 2) {
        int j0 = g_col[p], j1 = g_col[p + 1];
        float wa = di * g_w[p], wb = di * g_w[p + 1];
        uint2 v0 = hp2[(size_t)j0 * 64 + lane];
        uint2 v1 = hp2[(size_t)j1 * 64 + lane];
        float2 a0 = __half22float2(*(__half2*)&v0.x);
        float2 a1 = __half22float2(*(__half2*)&v0.y);
        float2 b0 = __half22float2(*(__half2*)&v1.x);
        float2 b1 = __half22float2(*(__half2*)&v1.y);
        acc0 = fmaf(wa, a0.x, acc0); acc1 = fmaf(wa, a0.y, acc1);
        acc2 = fmaf(wa, a1.x, acc2); acc3 = fmaf(wa, a1.y, acc3);
        acc0 = fmaf(wb, b0.x, acc0); acc1 = fmaf(wb, b0.y, acc1);
        acc2 = fmaf(wb, b1.x, acc2); acc3 = fmaf(wb, b1.y, acc3);
    }
    if (p < e) {
        int j0 = g_col[p];
        float wa = di * g_w[p];
        uint2 v0 = hp2[(size_t)j0 * 64 + lane];
        float2 a0 = __half22float2(*(__half2*)&v0.x);
        float2 a1 = __half22float2(*(__half2*)&v0.y);
        acc0 = fmaf(wa, a0.x, acc0); acc1 = fmaf(wa, a0.y, acc1);
        acc2 = fmaf(wa, a1.x, acc2); acc3 = fmaf(wa, a1.y, acc3);
    }
    float4 b = ((const float4*)bias)[lane];
    acc0 += b.x; acc1 += b.y; acc2 += b.z; acc3 += b.w;
    if (RELU) {
        acc0 = fmaxf(acc0, 0.f); acc1 = fmaxf(acc1, 0.f);
        acc2 = fmaxf(acc2, 0.f); acc3 = fmaxf(acc3, 0.f);
    }
    if (PACK) {
        __half h0 = __float2half_rn(acc0);
        __half h1 = __float2half_rn(acc1);
        __half h2 = __float2half_rn(acc2);
        __half h3 = __float2half_rn(acc3);
        __half2 hi0; hi0.x = h0; hi0.y = h1;
        __half2 hi1; hi1.x = h2; hi1.y = h3;
        __half2 lo0, lo1;
        lo0.x = __float2half_rn(acc0 - __half2float(h0));
        lo0.y = __float2half_rn(acc1 - __half2float(h1));
        lo1.x = __float2half_rn(acc2 - __half2float(h2));
        lo1.y = __float2half_rn(acc3 - __half2float(h3));
        __half* row = HoutH + (size_t)node * 512;
        *(__half2*)(row + 4 * lane)           = hi0;
        *(__half2*)(row + 4 * lane + 2)       = hi1;
        *(__half2*)(row + 256 + 4 * lane)     = lo0;
        *(__half2*)(row + 256 + 4 * lane + 2) = lo1;
    } else {
        ((float4*)HoutF)[(size_t)node * 64 + lane] =
            make_float4(acc0, acc1, acc2, acc3);
    }
}

// ---------------- pooling (batch is sorted) ----------------
__global__ void bounds_kernel(const int* __restrict__ batch) {
    int i = blockIdx.x * blockDim.x + threadIdx.x;
    if (i >= NN) return;
    int b = batch[i];
    int prev = (i == 0) ? -1 : batch[i - 1];
    for (int g = prev + 1; g <= b; g++) g_gstart[g] = i;
    if (i == NN - 1)
        for (int g = b + 1; g <= GG; g++) g_gstart[g] = NN;
}

__global__ void pool_kernel(const float* __restrict__ H) {
    int g = blockIdx.x;
    int c = threadIdx.x;
    int s = g_gstart[g];
    int e = g_gstart[g + 1];
    float acc = 0.0f;
    for (int i = s; i < e; i++) acc += H[(size_t)i * HD + c];
    float cnt = (float)(e - s);
    if (cnt < 1.0f) cnt = 1.0f;
    g_pooled[g * HD + c] = acc / cnt;
}

// ---------------- launch ----------------
extern "C" void kernel_launch(void* const* d_in, const int* in_sizes, int n_in,
                              void* d_out, int out_size) {
    const float* x     = (const float*)d_in[0];
    const int*   src   = (const int*)d_in[1];
    const int*   dst   = (const int*)d_in[2];
    const int*   batch = (const int*)d_in[3];
    const float* W1 = (const float*)d_in[4];
    const float* b1 = (const float*)d_in[5];
    const float* W2 = (const float*)d_in[6];
    const float* b2 = (const float*)d_in[7];
    const float* W3 = (const float*)d_in[8];
    const float* b3 = (const float*)d_in[9];
    const float* Wm1 = (const float*)d_in[10];
    const float* bm1 = (const float*)d_in[11];
    const float* Wm2 = (const float*)d_in[12];
    const float* bm2 = (const float*)d_in[13];
    float* out = (float*)d_out;

    float *h, *pooled, *mlp1;
    __half *t16, *a2, *b2p;
    cudaGetSymbolAddress((void**)&t16, g_t16);
    cudaGetSymbolAddress((void**)&h, g_h);
    cudaGetSymbolAddress((void**)&pooled, g_pooled);
    cudaGetSymbolAddress((void**)&mlp1, g_mlp1);
    cudaGetSymbolAddress((void**)&a2, g_a2);
    cudaGetSymbolAddress((void**)&b2p, g_b2);

    const int GSMEM = 3 * STAGE_BYTES;   // 92160
    cudaFuncSetAttribute(gemm_mma2_kernel,
                         cudaFuncAttributeMaxDynamicSharedMemorySize, GSMEM);

    const int TB = 256;
    const size_t BSTRIDE = (size_t)HD * 2 * HD;

    const int gemm_grid = (NN + 127) / 128;   // 782
    const int spmm_grid = (NN + 3) / 4;

    // --- front-load GEMM path so ncu's skip-N capture lands on gemm (4th launch) ---
    splitW_kernel<<<(FIN * HD + TB - 1) / TB, TB>>>(W1, b2p + 0 * BSTRIDE, FIN, HD);   // 1
    splitW_kernel<<<(HD * HD + TB - 1) / TB, TB>>>(W2, b2p + 1 * BSTRIDE, HD, HD);     // 2
    splitX_kernel<<<(NN * FIN / 2 + TB - 1) / TB, TB>>>(x, a2, NN, FIN);               // 3
    gemm_mma2_kernel<<<gemm_grid, 512, GSMEM>>>(a2, b2p + 0 * BSTRIDE, t16, NN, 2 * FIN); // 4 (profiled)
    splitW_kernel<<<(HD * HD + TB - 1) / TB, TB>>>(W3, b2p + 2 * BSTRIDE, HD, HD);     // 5

    // ----- CSR + degrees -----
    zero_deg_kernel<<<(NN + TB - 1) / TB, TB>>>();
    count_kernel<<<(EE + TB - 1) / TB, TB>>>(dst);
    scan_kernel<<<1, 1024>>>();
    dinv_kernel<<<(NN + TB - 1) / TB, TB>>>();
    scatter_kernel<<<(EE + TB - 1) / TB, TB>>>(src, dst);

    // ----- layer 1 aggregation (emit packed fp16) -----
    spmm16_kernel<true, true><<<spmm_grid, 256>>>(t16, b1, nullptr, a2);
    // ----- layer 2 -----
    gemm_mma2_kernel<<<gemm_grid, 512, GSMEM>>>(a2, b2p + 1 * BSTRIDE, t16, NN, 2 * HD);
    spmm16_kernel<true, true><<<spmm_grid, 256>>>(t16, b2, nullptr, a2);
    // ----- layer 3 (no relu; emit fp32 for pooling) -----
    gemm_mma2_kernel<<<gemm_grid, 512, GSMEM>>>(a2, b2p + 2 * BSTRIDE, t16, NN, 2 * HD);
    spmm16_kernel<false, false><<<spmm_grid, 256>>>(t16, b3, h, nullptr);

    // ----- pooling -----
    bounds_kernel<<<(NN + TB - 1) / TB, TB>>>(batch);
    pool_kernel<<<GG, HD>>>(h);

    // ----- MLP head -----
    dim3 mlp1_grid(NHID_ / 128, (GG + 127) / 128);
    sgemm_kernel<true, true><<<mlp1_grid, 256>>>(pooled, Wm1, bm1, mlp1, GG, HD, NHID_);
    dim3 mlp2_grid(NOUT_ / 128, (GG + 127) / 128);
    sgemm_kernel<true, false><<<mlp2_grid, 256>>>(mlp1, Wm2, bm2, out, GG, NHID_, NOUT_);
}

// round 7
// speedup vs baseline: 2.5244x; 1.2770x over previous
#include <cuda_runtime.h>
#include <cuda_fp16.h>
#include <math.h>
#include <stdint.h>

#define NN   100000
#define EE   1600000
#define FIN  128
#define HD   256
#define NHID_ 512
#define NOUT_ 256
#define GG   256

__device__ __forceinline__ uint32_t smem_u32(const void* p) {
    uint32_t a;
    asm("{ .reg .u64 t; cvta.to.shared.u64 t, %1; cvt.u32.u64 %0, t; }" : "=r"(a) : "l"(p));
    return a;
}

// ---------------- scratch (no allocation allowed) ----------------
__device__ __align__(256) __half g_t16[(size_t)NN * HD];     // GEMM out (fp16) / SpMM in
__device__ __align__(256) __half g_a16[(size_t)NN * HD];     // SpMM out (fp16) / GEMM A operand
__device__ __align__(256) float  g_h[(size_t)NN * HD];       // fp32 activations (layer3 / pooling)
__device__ __align__(256) __half g_wt[3][HD * HD];           // W^T fp16 per layer
__device__ int   g_deg[NN];
__device__ float g_dinv[NN];
__device__ int   g_rowoff[NN + 1];
__device__ int   g_cursor[NN];
__device__ int   g_col[EE];
__device__ float g_w[EE];
__device__ int   g_gstart[GG + 1];
__device__ float g_pooled[GG * HD];
__device__ float g_mlp1[GG * NHID_];

// ---------------- CSR construction ----------------
__global__ void zero_deg_kernel() {
    int i = blockIdx.x * blockDim.x + threadIdx.x;
    if (i < NN) g_deg[i] = 0;
}

__global__ void count_kernel(const int* __restrict__ dst) {
    int e = blockIdx.x * blockDim.x + threadIdx.x;
    if (e < EE) atomicAdd(&g_deg[dst[e]], 1);
}

__global__ void scan_kernel() {
    __shared__ int sh[1024];
    __shared__ int carry;
    int tid = threadIdx.x;
    if (tid == 0) carry = 0;
    __syncthreads();
    for (int base = 0; base < NN; base += 1024) {
        int i = base + tid;
        int v = (i < NN) ? g_deg[i] : 0;
        sh[tid] = v;
        __syncthreads();
        for (int off = 1; off < 1024; off <<= 1) {
            int t = (tid >= off) ? sh[tid - off] : 0;
            __syncthreads();
            sh[tid] += t;
            __syncthreads();
        }
        int excl = carry + sh[tid] - v;
        if (i < NN) { g_rowoff[i] = excl; g_cursor[i] = excl; }
        __syncthreads();
        if (tid == 1023) carry += sh[1023];
        __syncthreads();
    }
    if (tid == 0) g_rowoff[NN] = carry;
}

__global__ void dinv_kernel() {
    int i = blockIdx.x * blockDim.x + threadIdx.x;
    if (i < NN) g_dinv[i] = rsqrtf(1.0f + (float)g_deg[i]);
}

__global__ void scatter_kernel(const int* __restrict__ src, const int* __restrict__ dst) {
    int e = blockIdx.x * blockDim.x + threadIdx.x;
    if (e < EE) {
        int s = src[e];
        int p = atomicAdd(&g_cursor[dst[e]], 1);
        g_col[p] = s;
        g_w[p] = g_dinv[s];
    }
}

// ---------------- converts ----------------
// x [M,K] fp32 -> fp16
__global__ void convX_kernel(const float* __restrict__ A,
                             __half* __restrict__ A16, size_t n) {
    size_t i = (size_t)(blockIdx.x) * blockDim.x + threadIdx.x;
    if (i * 2 >= n) return;
    float2 a = *(const float2*)(A + i * 2);
    __half2 hp;
    hp.x = __float2half_rn(a.x);
    hp.y = __float2half_rn(a.y);
    *(__half2*)(A16 + i * 2) = hp;
}

// W [K,N] fp32 -> Wt [N,K] fp16 (transposed)
__global__ void splitW_kernel(const float* __restrict__ W,
                              __half* __restrict__ Wt, int K, int N) {
    int idx = blockIdx.x * blockDim.x + threadIdx.x;
    if (idx >= K * N) return;
    int k = idx / N, n = idx % N;
    Wt[(size_t)n * K + k] = __float2half_rn(W[idx]);
}

// ---------------- fp16 mma.sync GEMM: C16[M,256] = A16[M,K] @ Wt[256,K]^T ----------------
// BM=128, BN=256 (full), BK=32, 512 threads (16 warps, warp tile 32x64), 3-stage cp.async.
#define STAGE_BYTES 30720   // A: 128*80 = 10240 ; B: 256*80 = 20480
__global__ void __launch_bounds__(512, 1)
gemm_mma2_kernel(const __half* __restrict__ A16,
                 const __half* __restrict__ B16,
                 __half* __restrict__ C16, int M, int K)
{
    extern __shared__ char smem_raw[];
    const uint32_t base = smem_u32(smem_raw);

    const int tid  = threadIdx.x;
    const int wid  = tid >> 5;
    const int lane = tid & 31;
    const int m0 = blockIdx.x * 128;
    const int wm = (wid & 3) * 32;     // 0..96
    const int wn = (wid >> 2) * 64;    // 0..192

    float acc[2][8][4];
#pragma unroll
    for (int i = 0; i < 2; i++)
#pragma unroll
        for (int j = 0; j < 8; j++)
#pragma unroll
            for (int q = 0; q < 4; q++) acc[i][j][q] = 0.0f;

    const int NKB = K / 32;

    auto load_stage = [&](int kb, int s) {
        const uint32_t sb = base + (uint32_t)s * STAGE_BYTES;
        int k0 = kb * 32;
        {   // A: 512 x 16B
            int row = tid >> 2, seg = tid & 3;
            const __half* gp = A16 + (size_t)(m0 + row) * K + k0 + seg * 8;
            uint32_t d = sb + row * 80 + seg * 16;
            uint32_t sz = (m0 + row < M) ? 16u : 0u;
            asm volatile("cp.async.cg.shared.global [%0], [%1], 16, %2;"
                         :: "r"(d), "l"(gp), "r"(sz) : "memory");
        }
#pragma unroll
        for (int it = 0; it < 2; it++) {   // B: 1024 x 16B
            int u = tid + it * 512;
            int row = u >> 2, seg = u & 3;
            const __half* gp = B16 + (size_t)row * K + k0 + seg * 8;
            uint32_t d = sb + 10240 + row * 80 + seg * 16;
            asm volatile("cp.async.cg.shared.global [%0], [%1], 16;"
                         :: "r"(d), "l"(gp) : "memory");
        }
        asm volatile("cp.async.commit_group;" ::: "memory");
    };

    load_stage(0, 0);
    load_stage(1, 1);

    const int tg = lane >> 3;   // 0..3
    const int tr = lane & 7;    // 0..7

    for (int kb = 0; kb < NKB; kb++) {
        int s = kb % 3;
        if (kb + 2 < NKB) {
            load_stage(kb + 2, (kb + 2) % 3);
            asm volatile("cp.async.wait_group 2;" ::: "memory");
        } else if (kb + 1 < NKB) {
            asm volatile("cp.async.wait_group 1;" ::: "memory");
        } else {
            asm volatile("cp.async.wait_group 0;" ::: "memory");
        }
        __syncthreads();

        const uint32_t Ab = base + (uint32_t)s * STAGE_BYTES;
        const uint32_t Bb = Ab + 10240;

#pragma unroll
        for (int ks = 0; ks < 2; ks++) {
            int kb16 = ks * 16;
            uint32_t a[2][4];
#pragma unroll
            for (int mi = 0; mi < 2; mi++) {
                uint32_t addr = Ab + (wm + mi * 16 + tr + (tg & 1) * 8) * 80
                                   + (kb16 + (tg >> 1) * 8) * 2;
                asm volatile("ldmatrix.sync.aligned.m8n8.x4.shared.b16 {%0,%1,%2,%3}, [%4];"
                             : "=r"(a[mi][0]), "=r"(a[mi][1]), "=r"(a[mi][2]), "=r"(a[mi][3])
                             : "r"(addr));
            }
#pragma unroll
            for (int np = 0; np < 4; np++) {
                uint32_t b[4];
                uint32_t addr = Bb + (wn + np * 16 + (tg >> 1) * 8 + tr) * 80
                                   + (kb16 + (tg & 1) * 8) * 2;
                asm volatile("ldmatrix.sync.aligned.m8n8.x4.shared.b16 {%0,%1,%2,%3}, [%4];"
                             : "=r"(b[0]), "=r"(b[1]), "=r"(b[2]), "=r"(b[3])
                             : "r"(addr));
#pragma unroll
                for (int mi = 0; mi < 2; mi++) {
#pragma unroll
                    for (int hh = 0; hh < 2; hh++) {
                        float* c = acc[mi][np * 2 + hh];
                        asm volatile(
                            "mma.sync.aligned.m16n8k16.row.col.f32.f16.f16.f32 "
                            "{%0,%1,%2,%3}, {%4,%5,%6,%7}, {%8,%9}, {%0,%1,%2,%3};"
                            : "+f"(c[0]), "+f"(c[1]), "+f"(c[2]), "+f"(c[3])
                            : "r"(a[mi][0]), "r"(a[mi][1]), "r"(a[mi][2]), "r"(a[mi][3]),
                              "r"(b[hh * 2]), "r"(b[hh * 2 + 1]));
                    }
                }
            }
        }
        __syncthreads();
    }

    // epilogue: fp16 output
#pragma unroll
    for (int mi = 0; mi < 2; mi++) {
        int r0 = m0 + wm + mi * 16 + (lane >> 2);
#pragma unroll
        for (int ni = 0; ni < 8; ni++) {
            int cc = wn + ni * 8 + (lane & 3) * 2;
            float* c = acc[mi][ni];
            if (r0 < M) {
                __half2 v; v.x = __float2half_rn(c[0]); v.y = __float2half_rn(c[1]);
                *(__half2*)(C16 + (size_t)r0 * 256 + cc) = v;
            }
            if (r0 + 8 < M) {
                __half2 v; v.x = __float2half_rn(c[2]); v.y = __float2half_rn(c[3]);
                *(__half2*)(C16 + (size_t)(r0 + 8) * 256 + cc) = v;
            }
        }
    }
}

// ---------------- fp32 SGEMM (small MLP head only) ----------------
template <bool BIAS, bool RELU>
__global__ void __launch_bounds__(256)
sgemm_kernel(const float* __restrict__ A, const float* __restrict__ B,
             const float* __restrict__ bias, float* __restrict__ C,
             int M, int K, int N) {
    __shared__ float As[8][128];
    __shared__ float Bs[8][128];
    const int tid = threadIdx.x;
    const int m0 = blockIdx.y * 128;
    const int n0 = blockIdx.x * 128;

    const int arow = tid >> 1;
    const int acol = (tid & 1) * 4;
    const int bkrow = tid >> 5;
    const int bcol = (tid & 31) * 4;

    const int ty = tid >> 4;
    const int tx = tid & 15;

    float acc[8][8];
#pragma unroll
    for (int i = 0; i < 8; i++)
#pragma unroll
        for (int j = 0; j < 8; j++) acc[i][j] = 0.0f;

    for (int k0 = 0; k0 < K; k0 += 8) {
        float4 av = make_float4(0.f, 0.f, 0.f, 0.f);
        int gr = m0 + arow;
        if (gr < M) av = *(const float4*)(A + (size_t)gr * K + k0 + acol);
        As[acol + 0][arow] = av.x;
        As[acol + 1][arow] = av.y;
        As[acol + 2][arow] = av.z;
        As[acol + 3][arow] = av.w;
        float4 bv = *(const float4*)(B + (size_t)(k0 + bkrow) * N + n0 + bcol);
        *(float4*)&Bs[bkrow][bcol] = bv;
        __syncthreads();

#pragma unroll
        for (int kk = 0; kk < 8; kk++) {
            float ar[8], br[8];
            float4 a0 = *(const float4*)&As[kk][ty * 8];
            float4 a1 = *(const float4*)&As[kk][ty * 8 + 4];
            float4 b0 = *(const float4*)&Bs[kk][tx * 8];
            float4 b1 = *(const float4*)&Bs[kk][tx * 8 + 4];
            ar[0] = a0.x; ar[1] = a0.y; ar[2] = a0.z; ar[3] = a0.w;
            ar[4] = a1.x; ar[5] = a1.y; ar[6] = a1.z; ar[7] = a1.w;
            br[0] = b0.x; br[1] = b0.y; br[2] = b0.z; br[3] = b0.w;
            br[4] = b1.x; br[5] = b1.y; br[6] = b1.z; br[7] = b1.w;
#pragma unroll
            for (int i = 0; i < 8; i++)
#pragma unroll
                for (int j = 0; j < 8; j++)
                    acc[i][j] = fmaf(ar[i], br[j], acc[i][j]);
        }
        __syncthreads();
    }

#pragma unroll
    for (int i = 0; i < 8; i++) {
        int row = m0 + ty * 8 + i;
        if (row >= M) continue;
#pragma unroll
        for (int j = 0; j < 8; j++) {
            int colc = n0 + tx * 8 + j;
            float v = acc[i][j];
            if (BIAS) v += bias[colc];
            if (RELU) v = fmaxf(v, 0.0f);
            C[(size_t)row * N + colc] = v;
        }
    }
}

// ---------------- SpMM over fp16 rows + self-loop + bias (+relu) ----------------
// warp per node (8 nodes per 256-thread block); lane owns 8 channels (one uint4).
// PACK16: emit fp16 row; else emit fp32 row.
template <bool RELU, bool PACK16>
__global__ void __launch_bounds__(256)
spmm16_kernel(const __half* __restrict__ Hin, const float* __restrict__ bias,
              float* __restrict__ HoutF, __half* __restrict__ HoutH) {
    int node = blockIdx.x * 8 + (threadIdx.x >> 5);
    if (node >= NN) return;
    int lane = threadIdx.x & 31;
    float di = g_dinv[node];
    const uint4* hp = (const uint4*)Hin;   // 8 halves per uint4; 32 uint4 per 256-wide row

    float acc[8];
    {
        float w0 = di * di;
        uint4 v = hp[(size_t)node * 32 + lane];
        float2 f0 = __half22float2(*(__half2*)&v.x);
        float2 f1 = __half22float2(*(__half2*)&v.y);
        float2 f2 = __half22float2(*(__half2*)&v.z);
        float2 f3 = __half22float2(*(__half2*)&v.w);
        acc[0] = f0.x * w0; acc[1] = f0.y * w0;
        acc[2] = f1.x * w0; acc[3] = f1.y * w0;
        acc[4] = f2.x * w0; acc[5] = f2.y * w0;
        acc[6] = f3.x * w0; acc[7] = f3.y * w0;
    }

    int s = g_rowoff[node];
    int e = g_rowoff[node + 1];
    int p = s;
    for (; p + 2 <= e; p += 2) {
        int j0 = g_col[p], j1 = g_col[p + 1];
        float wa = di * g_w[p], wb = di * g_w[p + 1];
        uint4 v0 = hp[(size_t)j0 * 32 + lane];
        uint4 v1 = hp[(size_t)j1 * 32 + lane];
        {
            float2 f0 = __half22float2(*(__half2*)&v0.x);
            float2 f1 = __half22float2(*(__half2*)&v0.y);
            float2 f2 = __half22float2(*(__half2*)&v0.z);
            float2 f3 = __half22float2(*(__half2*)&v0.w);
            acc[0] = fmaf(wa, f0.x, acc[0]); acc[1] = fmaf(wa, f0.y, acc[1]);
            acc[2] = fmaf(wa, f1.x, acc[2]); acc[3] = fmaf(wa, f1.y, acc[3]);
            acc[4] = fmaf(wa, f2.x, acc[4]); acc[5] = fmaf(wa, f2.y, acc[5]);
            acc[6] = fmaf(wa, f3.x, acc[6]); acc[7] = fmaf(wa, f3.y, acc[7]);
        }
        {
            float2 f0 = __half22float2(*(__half2*)&v1.x);
            float2 f1 = __half22float2(*(__half2*)&v1.y);
            float2 f2 = __half22float2(*(__half2*)&v1.z);
            float2 f3 = __half22float2(*(__half2*)&v1.w);
            acc[0] = fmaf(wb, f0.x, acc[0]); acc[1] = fmaf(wb, f0.y, acc[1]);
            acc[2] = fmaf(wb, f1.x, acc[2]); acc[3] = fmaf(wb, f1.y, acc[3]);
            acc[4] = fmaf(wb, f2.x, acc[4]); acc[5] = fmaf(wb, f2.y, acc[5]);
            acc[6] = fmaf(wb, f3.x, acc[6]); acc[7] = fmaf(wb, f3.y, acc[7]);
        }
    }
    if (p < e) {
        int j0 = g_col[p];
        float wa = di * g_w[p];
        uint4 v0 = hp[(size_t)j0 * 32 + lane];
        float2 f0 = __half22float2(*(__half2*)&v0.x);
        float2 f1 = __half22float2(*(__half2*)&v0.y);
        float2 f2 = __half22float2(*(__half2*)&v0.z);
        float2 f3 = __half22float2(*(__half2*)&v0.w);
        acc[0] = fmaf(wa, f0.x, acc[0]); acc[1] = fmaf(wa, f0.y, acc[1]);
        acc[2] = fmaf(wa, f1.x, acc[2]); acc[3] = fmaf(wa, f1.y, acc[3]);
        acc[4] = fmaf(wa, f2.x, acc[4]); acc[5] = fmaf(wa, f2.y, acc[5]);
        acc[6] = fmaf(wa, f3.x, acc[6]); acc[7] = fmaf(wa, f3.y, acc[7]);
    }

    const float4* bp = (const float4*)(bias) + lane * 2;
    float4 b0 = bp[0], b1 = bp[1];
    acc[0] += b0.x; acc[1] += b0.y; acc[2] += b0.z; acc[3] += b0.w;
    acc[4] += b1.x; acc[5] += b1.y; acc[6] += b1.z; acc[7] += b1.w;
    if (RELU) {
#pragma unroll
        for (int i = 0; i < 8; i++) acc[i] = fmaxf(acc[i], 0.0f);
    }
    if (PACK16) {
        uint4 o;
        __half2 t;
        t.x = __float2half_rn(acc[0]); t.y = __float2half_rn(acc[1]); o.x = *(uint32_t*)&t;
        t.x = __float2half_rn(acc[2]); t.y = __float2half_rn(acc[3]); o.y = *(uint32_t*)&t;
        t.x = __float2half_rn(acc[4]); t.y = __float2half_rn(acc[5]); o.z = *(uint32_t*)&t;
        t.x = __float2half_rn(acc[6]); t.y = __float2half_rn(acc[7]); o.w = *(uint32_t*)&t;
        ((uint4*)HoutH)[(size_t)node * 32 + lane] = o;
    } else {
        float4* op = (float4*)HoutF + (size_t)node * 64 + lane * 2;
        op[0] = make_float4(acc[0], acc[1], acc[2], acc[3]);
        op[1] = make_float4(acc[4], acc[5], acc[6], acc[7]);
    }
}

// ---------------- pooling (batch is sorted) ----------------
__global__ void bounds_kernel(const int* __restrict__ batch) {
    int i = blockIdx.x * blockDim.x + threadIdx.x;
    if (i >= NN) return;
    int b = batch[i];
    int prev = (i == 0) ? -1 : batch[i - 1];
    for (int g = prev + 1; g <= b; g++) g_gstart[g] = i;
    if (i == NN - 1)
        for (int g = b + 1; g <= GG; g++) g_gstart[g] = NN;
}

__global__ void pool_kernel(const float* __restrict__ H) {
    int g = blockIdx.x;
    int c = threadIdx.x;
    int s = g_gstart[g];
    int e = g_gstart[g + 1];
    float acc = 0.0f;
    for (int i = s; i < e; i++) acc += H[(size_t)i * HD + c];
    float cnt = (float)(e - s);
    if (cnt < 1.0f) cnt = 1.0f;
    g_pooled[g * HD + c] = acc / cnt;
}

// ---------------- launch ----------------
extern "C" void kernel_launch(void* const* d_in, const int* in_sizes, int n_in,
                              void* d_out, int out_size) {
    const float* x     = (const float*)d_in[0];
    const int*   src   = (const int*)d_in[1];
    const int*   dst   = (const int*)d_in[2];
    const int*   batch = (const int*)d_in[3];
    const float* W1 = (const float*)d_in[4];
    const float* b1 = (const float*)d_in[5];
    const float* W2 = (const float*)d_in[6];
    const float* b2 = (const float*)d_in[7];
    const float* W3 = (const float*)d_in[8];
    const float* b3 = (const float*)d_in[9];
    const float* Wm1 = (const float*)d_in[10];
    const float* bm1 = (const float*)d_in[11];
    const float* Wm2 = (const float*)d_in[12];
    const float* bm2 = (const float*)d_in[13];
    float* out = (float*)d_out;

    float *h, *pooled, *mlp1;
    __half *t16, *a16, *wt;
    cudaGetSymbolAddress((void**)&t16, g_t16);
    cudaGetSymbolAddress((void**)&a16, g_a16);
    cudaGetSymbolAddress((void**)&h, g_h);
    cudaGetSymbolAddress((void**)&pooled, g_pooled);
    cudaGetSymbolAddress((void**)&mlp1, g_mlp1);
    cudaGetSymbolAddress((void**)&wt, g_wt);

    const int GSMEM = 3 * STAGE_BYTES;   // 92160
    cudaFuncSetAttribute(gemm_mma2_kernel,
                         cudaFuncAttributeMaxDynamicSharedMemorySize, GSMEM);

    const int TB = 256;
    const size_t WSTRIDE = (size_t)HD * HD;

    const int gemm_grid = (NN + 127) / 128;   // 782
    const int spmm_grid = (NN + 7) / 8;

    // --- front-load GEMM path so ncu's skip-N capture lands on gemm (4th launch) ---
    splitW_kernel<<<(FIN * HD + TB - 1) / TB, TB>>>(W1, wt + 0 * WSTRIDE, FIN, HD);   // 1
    splitW_kernel<<<(HD * HD + TB - 1) / TB, TB>>>(W2, wt + 1 * WSTRIDE, HD, HD);     // 2
    convX_kernel<<<(int)(((size_t)NN * FIN / 2 + TB - 1) / TB), TB>>>(x, a16, (size_t)NN * FIN); // 3
    gemm_mma2_kernel<<<gemm_grid, 512, GSMEM>>>(a16, wt + 0 * WSTRIDE, t16, NN, FIN); // 4 (profiled)
    splitW_kernel<<<(HD * HD + TB - 1) / TB, TB>>>(W3, wt + 2 * WSTRIDE, HD, HD);     // 5

    // ----- CSR + degrees -----
    zero_deg_kernel<<<(NN + TB - 1) / TB, TB>>>();
    count_kernel<<<(EE + TB - 1) / TB, TB>>>(dst);
    scan_kernel<<<1, 1024>>>();
    dinv_kernel<<<(NN + TB - 1) / TB, TB>>>();
    scatter_kernel<<<(EE + TB - 1) / TB, TB>>>(src, dst);

    // ----- layer 1 aggregation (emit fp16) -----
    spmm16_kernel<true, true><<<spmm_grid, 256>>>(t16, b1, nullptr, a16);
    // ----- layer 2 -----
    gemm_mma2_kernel<<<gemm_grid, 512, GSMEM>>>(a16, wt + 1 * WSTRIDE, t16, NN, HD);
    spmm16_kernel<true, true><<<spmm_grid, 256>>>(t16, b2, nullptr, a16);
    // ----- layer 3 (no relu; emit fp32 for pooling) -----
    gemm_mma2_kernel<<<gemm_grid, 512, GSMEM>>>(a16, wt + 2 * WSTRIDE, t16, NN, HD);
    spmm16_kernel<false, false><<<spmm_grid, 256>>>(t16, b3, h, nullptr);

    // ----- pooling -----
    bounds_kernel<<<(NN + TB - 1) / TB, TB>>>(batch);
    pool_kernel<<<GG, HD>>>(h);

    // ----- MLP head -----
    dim3 mlp1_grid(NHID_ / 128, (GG + 127) / 128);
    sgemm_kernel<true, true><<<mlp1_grid, 256>>>(pooled, Wm1, bm1, mlp1, GG, HD, NHID_);
    dim3 mlp2_grid(NOUT_ / 128, (GG + 127) / 128);
    sgemm_kernel<true, false><<<mlp2_grid, 256>>>(mlp1, Wm2, bm2, out, GG, NHID_, NOUT_);
}

// round 8
// speedup vs baseline: 3.0721x; 1.2170x over previous
#include <cuda_runtime.h>
#include <cuda_fp16.h>
#include <math.h>
#include <stdint.h>

#define NN   100000
#define EE   1600000
#define FIN  128
#define HD   256
#define NHID_ 512
#define NOUT_ 256
#define GG   256
#define NPART 98   // ceil(NN/1024)

__device__ __forceinline__ uint32_t smem_u32(const void* p) {
    uint32_t a;
    asm("{ .reg .u64 t; cvta.to.shared.u64 t, %1; cvt.u32.u64 %0, t; }" : "=r"(a) : "l"(p));
    return a;
}

// ---------------- scratch (no allocation allowed) ----------------
__device__ __align__(256) __half g_t16[(size_t)NN * HD];     // GEMM out (fp16) / SpMM in
__device__ __align__(256) __half g_a16[(size_t)NN * HD];     // SpMM out (fp16) / GEMM A operand / pool in
__device__ __align__(256) __half g_wt[3][HD * HD];           // W^T fp16 per layer
__device__ int   g_deg[NN];
__device__ float g_dinv[NN];
__device__ int   g_rowoff[NN + 1];
__device__ int   g_cursor[NN];
__device__ int   g_col[EE];
__device__ float g_w[EE];
__device__ int   g_part[NPART];
__device__ int   g_poff[NPART];
__device__ int   g_gstart[GG + 1];
__device__ float g_pooled[GG * HD];
__device__ float g_mlp1[GG * NHID_];

// ---------------- CSR construction ----------------
__global__ void zero_deg_kernel() {
    int i = blockIdx.x * blockDim.x + threadIdx.x;
    if (i < NN) g_deg[i] = 0;
}

__global__ void count_kernel(const int* __restrict__ dst) {
    int e = blockIdx.x * blockDim.x + threadIdx.x;
    if (e < EE) atomicAdd(&g_deg[dst[e]], 1);
}

// block partial sums of g_deg (1024 per block)
__global__ void partial_kernel() {
    __shared__ int sh[1024];
    int i = blockIdx.x * 1024 + threadIdx.x;
    sh[threadIdx.x] = (i < NN) ? g_deg[i] : 0;
    __syncthreads();
    for (int off = 512; off > 0; off >>= 1) {
        if (threadIdx.x < off) sh[threadIdx.x] += sh[threadIdx.x + off];
        __syncthreads();
    }
    if (threadIdx.x == 0) g_part[blockIdx.x] = sh[0];
}

// 1-block exclusive scan of NPART partials
__global__ void scanpart_kernel() {
    __shared__ int sh[128];
    int tid = threadIdx.x;
    int v = (tid < NPART) ? g_part[tid] : 0;
    sh[tid] = v;
    __syncthreads();
    for (int off = 1; off < 128; off <<= 1) {
        int t = (tid >= off) ? sh[tid - off] : 0;
        __syncthreads();
        sh[tid] += t;
        __syncthreads();
    }
    if (tid < NPART) g_poff[tid] = sh[tid] - v;
    if (tid == 127) g_rowoff[NN] = sh[127];
}

// per-block local scan + global offset -> rowoff/cursor
__global__ void apply_kernel() {
    __shared__ int sh[1024];
    int tid = threadIdx.x;
    int i = blockIdx.x * 1024 + tid;
    int v = (i < NN) ? g_deg[i] : 0;
    sh[tid] = v;
    __syncthreads();
    for (int off = 1; off < 1024; off <<= 1) {
        int t = (tid >= off) ? sh[tid - off] : 0;
        __syncthreads();
        sh[tid] += t;
        __syncthreads();
    }
    if (i < NN) {
        int excl = sh[tid] - v + g_poff[blockIdx.x];
        g_rowoff[i] = excl;
        g_cursor[i] = excl;
    }
}

__global__ void dinv_kernel() {
    int i = blockIdx.x * blockDim.x + threadIdx.x;
    if (i < NN) g_dinv[i] = rsqrtf(1.0f + (float)g_deg[i]);
}

__global__ void scatter_kernel(const int* __restrict__ src, const int* __restrict__ dst) {
    int e = blockIdx.x * blockDim.x + threadIdx.x;
    if (e < EE) {
        int s = src[e];
        int p = atomicAdd(&g_cursor[dst[e]], 1);
        g_col[p] = s;
        g_w[p] = g_dinv[s];
    }
}

// ---------------- converts ----------------
__global__ void convX_kernel(const float* __restrict__ A,
                             __half* __restrict__ A16, size_t n) {
    size_t i = (size_t)(blockIdx.x) * blockDim.x + threadIdx.x;
    if (i * 2 >= n) return;
    float2 a = *(const float2*)(A + i * 2);
    __half2 hp;
    hp.x = __float2half_rn(a.x);
    hp.y = __float2half_rn(a.y);
    *(__half2*)(A16 + i * 2) = hp;
}

// W [K,N] fp32 -> Wt [N,K] fp16 (transposed)
__global__ void splitW_kernel(const float* __restrict__ W,
                              __half* __restrict__ Wt, int K, int N) {
    int idx = blockIdx.x * blockDim.x + threadIdx.x;
    if (idx >= K * N) return;
    int k = idx / N, n = idx % N;
    Wt[(size_t)n * K + k] = __float2half_rn(W[idx]);
}

// ---------------- fp16 mma.sync GEMM: C16[M,256] = A16[M,K] @ Wt[256,K]^T ----------------
// BM=128, BN=256, BK=32, 512 threads (16 warps, warp tile 32x64), 5-stage cp.async,
// single __syncthreads per K-block (write stage != any stage read by prior iteration).
#define STAGE_BYTES 30720   // A: 128*80 = 10240 ; B: 256*80 = 20480
#define NSTAGE 5
__global__ void __launch_bounds__(512, 1)
gemm_mma2_kernel(const __half* __restrict__ A16,
                 const __half* __restrict__ B16,
                 __half* __restrict__ C16, int M, int K)
{
    extern __shared__ char smem_raw[];
    const uint32_t base = smem_u32(smem_raw);

    const int tid  = threadIdx.x;
    const int wid  = tid >> 5;
    const int lane = tid & 31;
    const int m0 = blockIdx.x * 128;
    const int wm = (wid & 3) * 32;     // 0..96
    const int wn = (wid >> 2) * 64;    // 0..192

    float acc[2][8][4];
#pragma unroll
    for (int i = 0; i < 2; i++)
#pragma unroll
        for (int j = 0; j < 8; j++)
#pragma unroll
            for (int q = 0; q < 4; q++) acc[i][j][q] = 0.0f;

    const int NKB = K / 32;

    auto load_stage = [&](int kb, int s) {
        const uint32_t sb = base + (uint32_t)s * STAGE_BYTES;
        int k0 = kb * 32;
        {   // A: 512 x 16B
            int row = tid >> 2, seg = tid & 3;
            const __half* gp = A16 + (size_t)(m0 + row) * K + k0 + seg * 8;
            uint32_t d = sb + row * 80 + seg * 16;
            uint32_t sz = (m0 + row < M) ? 16u : 0u;
            asm volatile("cp.async.cg.shared.global [%0], [%1], 16, %2;"
                         :: "r"(d), "l"(gp), "r"(sz) : "memory");
        }
#pragma unroll
        for (int it = 0; it < 2; it++) {   // B: 1024 x 16B
            int u = tid + it * 512;
            int row = u >> 2, seg = u & 3;
            const __half* gp = B16 + (size_t)row * K + k0 + seg * 8;
            uint32_t d = sb + 10240 + row * 80 + seg * 16;
            asm volatile("cp.async.cg.shared.global [%0], [%1], 16;"
                         :: "r"(d), "l"(gp) : "memory");
        }
        asm volatile("cp.async.commit_group;" ::: "memory");
    };

    // preload up to 4 stages
    for (int s = 0; s < 4 && s < NKB; s++) load_stage(s, s);

    const int tg = lane >> 3;   // 0..3
    const int tr = lane & 7;    // 0..7

    for (int kb = 0; kb < NKB; kb++) {
        int rem = NKB - 1 - kb;   // groups still pending after kb's completes
        if (rem >= 3)      asm volatile("cp.async.wait_group 3;" ::: "memory");
        else if (rem == 2) asm volatile("cp.async.wait_group 2;" ::: "memory");
        else if (rem == 1) asm volatile("cp.async.wait_group 1;" ::: "memory");
        else               asm volatile("cp.async.wait_group 0;" ::: "memory");
        __syncthreads();
        if (kb + 4 < NKB) load_stage(kb + 4, (kb + 4) % NSTAGE);

        const int s = kb % NSTAGE;
        const uint32_t Ab = base + (uint32_t)s * STAGE_BYTES;
        const uint32_t Bb = Ab + 10240;

#pragma unroll
        for (int ks = 0; ks < 2; ks++) {
            int kb16 = ks * 16;
            uint32_t a[2][4];
#pragma unroll
            for (int mi = 0; mi < 2; mi++) {
                uint32_t addr = Ab + (wm + mi * 16 + tr + (tg & 1) * 8) * 80
                                   + (kb16 + (tg >> 1) * 8) * 2;
                asm volatile("ldmatrix.sync.aligned.m8n8.x4.shared.b16 {%0,%1,%2,%3}, [%4];"
                             : "=r"(a[mi][0]), "=r"(a[mi][1]), "=r"(a[mi][2]), "=r"(a[mi][3])
                             : "r"(addr));
            }
#pragma unroll
            for (int np = 0; np < 4; np++) {
                uint32_t b[4];
                uint32_t addr = Bb + (wn + np * 16 + (tg >> 1) * 8 + tr) * 80
                                   + (kb16 + (tg & 1) * 8) * 2;
                asm volatile("ldmatrix.sync.aligned.m8n8.x4.shared.b16 {%0,%1,%2,%3}, [%4];"
                             : "=r"(b[0]), "=r"(b[1]), "=r"(b[2]), "=r"(b[3])
                             : "r"(addr));
#pragma unroll
                for (int mi = 0; mi < 2; mi++) {
#pragma unroll
                    for (int hh = 0; hh < 2; hh++) {
                        float* c = acc[mi][np * 2 + hh];
                        asm volatile(
                            "mma.sync.aligned.m16n8k16.row.col.f32.f16.f16.f32 "
                            "{%0,%1,%2,%3}, {%4,%5,%6,%7}, {%8,%9}, {%0,%1,%2,%3};"
                            : "+f"(c[0]), "+f"(c[1]), "+f"(c[2]), "+f"(c[3])
                            : "r"(a[mi][0]), "r"(a[mi][1]), "r"(a[mi][2]), "r"(a[mi][3]),
                              "r"(b[hh * 2]), "r"(b[hh * 2 + 1]));
                    }
                }
            }
        }
    }

    // epilogue: fp16 output
#pragma unroll
    for (int mi = 0; mi < 2; mi++) {
        int r0 = m0 + wm + mi * 16 + (lane >> 2);
#pragma unroll
        for (int ni = 0; ni < 8; ni++) {
            int cc = wn + ni * 8 + (lane & 3) * 2;
            float* c = acc[mi][ni];
            if (r0 < M) {
                __half2 v; v.x = __float2half_rn(c[0]); v.y = __float2half_rn(c[1]);
                *(__half2*)(C16 + (size_t)r0 * 256 + cc) = v;
            }
            if (r0 + 8 < M) {
                __half2 v; v.x = __float2half_rn(c[2]); v.y = __float2half_rn(c[3]);
                *(__half2*)(C16 + (size_t)(r0 + 8) * 256 + cc) = v;
            }
        }
    }
}

// ---------------- fp32 SGEMM (small MLP head only) ----------------
template <bool BIAS, bool RELU>
__global__ void __launch_bounds__(256)
sgemm_kernel(const float* __restrict__ A, const float* __restrict__ B,
             const float* __restrict__ bias, float* __restrict__ C,
             int M, int K, int N) {
    __shared__ float As[8][128];
    __shared__ float Bs[8][128];
    const int tid = threadIdx.x;
    const int m0 = blockIdx.y * 128;
    const int n0 = blockIdx.x * 128;

    const int arow = tid >> 1;
    const int acol = (tid & 1) * 4;
    const int bkrow = tid >> 5;
    const int bcol = (tid & 31) * 4;

    const int ty = tid >> 4;
    const int tx = tid & 15;

    float acc[8][8];
#pragma unroll
    for (int i = 0; i < 8; i++)
#pragma unroll
        for (int j = 0; j < 8; j++) acc[i][j] = 0.0f;

    for (int k0 = 0; k0 < K; k0 += 8) {
        float4 av = make_float4(0.f, 0.f, 0.f, 0.f);
        int gr = m0 + arow;
        if (gr < M) av = *(const float4*)(A + (size_t)gr * K + k0 + acol);
        As[acol + 0][arow] = av.x;
        As[acol + 1][arow] = av.y;
        As[acol + 2][arow] = av.z;
        As[acol + 3][arow] = av.w;
        float4 bv = *(const float4*)(B + (size_t)(k0 + bkrow) * N + n0 + bcol);
        *(float4*)&Bs[bkrow][bcol] = bv;
        __syncthreads();

#pragma unroll
        for (int kk = 0; kk < 8; kk++) {
            float ar[8], br[8];
            float4 a0 = *(const float4*)&As[kk][ty * 8];
            float4 a1 = *(const float4*)&As[kk][ty * 8 + 4];
            float4 b0 = *(const float4*)&Bs[kk][tx * 8];
            float4 b1 = *(const float4*)&Bs[kk][tx * 8 + 4];
            ar[0] = a0.x; ar[1] = a0.y; ar[2] = a0.z; ar[3] = a0.w;
            ar[4] = a1.x; ar[5] = a1.y; ar[6] = a1.z; ar[7] = a1.w;
            br[0] = b0.x; br[1] = b0.y; br[2] = b0.z; br[3] = b0.w;
            br[4] = b1.x; br[5] = b1.y; br[6] = b1.z; br[7] = b1.w;
#pragma unroll
            for (int i = 0; i < 8; i++)
#pragma unroll
                for (int j = 0; j < 8; j++)
                    acc[i][j] = fmaf(ar[i], br[j], acc[i][j]);
        }
        __syncthreads();
    }

#pragma unroll
    for (int i = 0; i < 8; i++) {
        int row = m0 + ty * 8 + i;
        if (row >= M) continue;
#pragma unroll
        for (int j = 0; j < 8; j++) {
            int colc = n0 + tx * 8 + j;
            float v = acc[i][j];
            if (BIAS) v += bias[colc];
            if (RELU) v = fmaxf(v, 0.0f);
            C[(size_t)row * N + colc] = v;
        }
    }
}

// ---------------- SpMM over fp16 rows + self-loop + bias (+relu), fp16 out ----------------
// warp per node (8 nodes per 256-thread block); lane owns 8 channels (one uint4).
template <bool RELU>
__global__ void __launch_bounds__(256)
spmm16_kernel(const __half* __restrict__ Hin, const float* __restrict__ bias,
              __half* __restrict__ Hout) {
    int node = blockIdx.x * 8 + (threadIdx.x >> 5);
    if (node >= NN) return;
    int lane = threadIdx.x & 31;
    float di = g_dinv[node];
    const uint4* hp = (const uint4*)Hin;   // 8 halves per uint4; 32 uint4 per 256-wide row

    float acc[8];
    {
        float w0 = di * di;
        uint4 v = hp[(size_t)node * 32 + lane];
        float2 f0 = __half22float2(*(__half2*)&v.x);
        float2 f1 = __half22float2(*(__half2*)&v.y);
        float2 f2 = __half22float2(*(__half2*)&v.z);
        float2 f3 = __half22float2(*(__half2*)&v.w);
        acc[0] = f0.x * w0; acc[1] = f0.y * w0;
        acc[2] = f1.x * w0; acc[3] = f1.y * w0;
        acc[4] = f2.x * w0; acc[5] = f2.y * w0;
        acc[6] = f3.x * w0; acc[7] = f3.y * w0;
    }

    int s = g_rowoff[node];
    int e = g_rowoff[node + 1];
    int p = s;

#define ACC_ROW(vv, ww) do { \
        float2 f0 = __half22float2(*(__half2*)&(vv).x); \
        float2 f1 = __half22float2(*(__half2*)&(vv).y); \
        float2 f2 = __half22float2(*(__half2*)&(vv).z); \
        float2 f3 = __half22float2(*(__half2*)&(vv).w); \
        acc[0] = fmaf((ww), f0.x, acc[0]); acc[1] = fmaf((ww), f0.y, acc[1]); \
        acc[2] = fmaf((ww), f1.x, acc[2]); acc[3] = fmaf((ww), f1.y, acc[3]); \
        acc[4] = fmaf((ww), f2.x, acc[4]); acc[5] = fmaf((ww), f2.y, acc[5]); \
        acc[6] = fmaf((ww), f3.x, acc[6]); acc[7] = fmaf((ww), f3.y, acc[7]); \
    } while (0)

    for (; p + 4 <= e; p += 4) {
        int j0 = g_col[p], j1 = g_col[p + 1], j2 = g_col[p + 2], j3 = g_col[p + 3];
        float w0 = di * g_w[p], w1 = di * g_w[p + 1];
        float w2 = di * g_w[p + 2], w3 = di * g_w[p + 3];
        uint4 v0 = hp[(size_t)j0 * 32 + lane];
        uint4 v1 = hp[(size_t)j1 * 32 + lane];
        uint4 v2 = hp[(size_t)j2 * 32 + lane];
        uint4 v3 = hp[(size_t)j3 * 32 + lane];
        ACC_ROW(v0, w0);
        ACC_ROW(v1, w1);
        ACC_ROW(v2, w2);
        ACC_ROW(v3, w3);
    }
    for (; p < e; p++) {
        int j0 = g_col[p];
        float w0 = di * g_w[p];
        uint4 v0 = hp[(size_t)j0 * 32 + lane];
        ACC_ROW(v0, w0);
    }
#undef ACC_ROW

    const float4* bp = (const float4*)(bias) + lane * 2;
    float4 b0 = bp[0], b1 = bp[1];
    acc[0] += b0.x; acc[1] += b0.y; acc[2] += b0.z; acc[3] += b0.w;
    acc[4] += b1.x; acc[5] += b1.y; acc[6] += b1.z; acc[7] += b1.w;
    if (RELU) {
#pragma unroll
        for (int i = 0; i < 8; i++) acc[i] = fmaxf(acc[i], 0.0f);
    }
    uint4 o;
    __half2 t;
    t.x = __float2half_rn(acc[0]); t.y = __float2half_rn(acc[1]); o.x = *(uint32_t*)&t;
    t.x = __float2half_rn(acc[2]); t.y = __float2half_rn(acc[3]); o.y = *(uint32_t*)&t;
    t.x = __float2half_rn(acc[4]); t.y = __float2half_rn(acc[5]); o.z = *(uint32_t*)&t;
    t.x = __float2half_rn(acc[6]); t.y = __float2half_rn(acc[7]); o.w = *(uint32_t*)&t;
    ((uint4*)Hout)[(size_t)node * 32 + lane] = o;
}

// ---------------- pooling (batch is sorted), fp16 input ----------------
__global__ void bounds_kernel(const int* __restrict__ batch) {
    int i = blockIdx.x * blockDim.x + threadIdx.x;
    if (i >= NN) return;
    int b = batch[i];
    int prev = (i == 0) ? -1 : batch[i - 1];
    for (int g = prev + 1; g <= b; g++) g_gstart[g] = i;
    if (i == NN - 1)
        for (int g = b + 1; g <= GG; g++) g_gstart[g] = NN;
}

__global__ void pool16_kernel(const __half* __restrict__ H) {
    int g = blockIdx.x;
    int c = threadIdx.x;
    int s = g_gstart[g];
    int e = g_gstart[g + 1];
    float acc = 0.0f;
    for (int i = s; i < e; i++) acc += __half2float(H[(size_t)i * HD + c]);
    float cnt = (float)(e - s);
    if (cnt < 1.0f) cnt = 1.0f;
    g_pooled[g * HD + c] = acc / cnt;
}

// ---------------- launch ----------------
extern "C" void kernel_launch(void* const* d_in, const int* in_sizes, int n_in,
                              void* d_out, int out_size) {
    const float* x     = (const float*)d_in[0];
    const int*   src   = (const int*)d_in[1];
    const int*   dst   = (const int*)d_in[2];
    const int*   batch = (const int*)d_in[3];
    const float* W1 = (const float*)d_in[4];
    const float* b1 = (const float*)d_in[5];
    const float* W2 = (const float*)d_in[6];
    const float* b2 = (const float*)d_in[7];
    const float* W3 = (const float*)d_in[8];
    const float* b3 = (const float*)d_in[9];
    const float* Wm1 = (const float*)d_in[10];
    const float* bm1 = (const float*)d_in[11];
    const float* Wm2 = (const float*)d_in[12];
    const float* bm2 = (const float*)d_in[13];
    float* out = (float*)d_out;

    float *pooled, *mlp1;
    __half *t16, *a16, *wt;
    cudaGetSymbolAddress((void**)&t16, g_t16);
    cudaGetSymbolAddress((void**)&a16, g_a16);
    cudaGetSymbolAddress((void**)&pooled, g_pooled);
    cudaGetSymbolAddress((void**)&mlp1, g_mlp1);
    cudaGetSymbolAddress((void**)&wt, g_wt);

    const int GSMEM = NSTAGE * STAGE_BYTES;   // 153600
    cudaFuncSetAttribute(gemm_mma2_kernel,
                         cudaFuncAttributeMaxDynamicSharedMemorySize, GSMEM);

    const int TB = 256;
    const size_t WSTRIDE = (size_t)HD * HD;

    const int gemm_grid = (NN + 127) / 128;   // 782
    const int spmm_grid = (NN + 7) / 8;

    // --- front-load GEMM path so ncu's skip-N capture lands on gemm (4th launch) ---
    splitW_kernel<<<(FIN * HD + TB - 1) / TB, TB>>>(W1, wt + 0 * WSTRIDE, FIN, HD);   // 1
    splitW_kernel<<<(HD * HD + TB - 1) / TB, TB>>>(W2, wt + 1 * WSTRIDE, HD, HD);     // 2
    convX_kernel<<<(int)(((size_t)NN * FIN / 2 + TB - 1) / TB), TB>>>(x, a16, (size_t)NN * FIN); // 3
    gemm_mma2_kernel<<<gemm_grid, 512, GSMEM>>>(a16, wt + 0 * WSTRIDE, t16, NN, FIN); // 4 (profiled)
    splitW_kernel<<<(HD * HD + TB - 1) / TB, TB>>>(W3, wt + 2 * WSTRIDE, HD, HD);     // 5

    // ----- CSR + degrees -----
    zero_deg_kernel<<<(NN + TB - 1) / TB, TB>>>();
    count_kernel<<<(EE + TB - 1) / TB, TB>>>(dst);
    partial_kernel<<<NPART, 1024>>>();
    scanpart_kernel<<<1, 128>>>();
    apply_kernel<<<NPART, 1024>>>();
    dinv_kernel<<<(NN + TB - 1) / TB, TB>>>();
    scatter_kernel<<<(EE + TB - 1) / TB, TB>>>(src, dst);

    // ----- layer 1 aggregation (fp16 out) -----
    spmm16_kernel<true><<<spmm_grid, 256>>>(t16, b1, a16);
    // ----- layer 2 -----
    gemm_mma2_kernel<<<gemm_grid, 512, GSMEM>>>(a16, wt + 1 * WSTRIDE, t16, NN, HD);
    spmm16_kernel<true><<<spmm_grid, 256>>>(t16, b2, a16);
    // ----- layer 3 (no relu; fp16 out for pooling) -----
    gemm_mma2_kernel<<<gemm_grid, 512, GSMEM>>>(a16, wt + 2 * WSTRIDE, t16, NN, HD);
    spmm16_kernel<false><<<spmm_grid, 256>>>(t16, b3, a16);

    // ----- pooling -----
    bounds_kernel<<<(NN + TB - 1) / TB, TB>>>(batch);
    pool16_kernel<<<GG, HD>>>(a16);

    // ----- MLP head -----
    dim3 mlp1_grid(NHID_ / 128, (GG + 127) / 128);
    sgemm_kernel<true, true><<<mlp1_grid, 256>>>(pooled, Wm1, bm1, mlp1, GG, HD, NHID_);
    dim3 mlp2_grid(NOUT_ / 128, (GG + 127) / 128);
    sgemm_kernel<true, false><<<mlp2_grid, 256>>>(mlp1, Wm2, bm2, out, GG, NHID_, NOUT_);
}

// round 9
// speedup vs baseline: 4.2448x; 1.3817x over previous
#include <cuda_runtime.h>
#include <cuda_fp16.h>
#include <math.h>
#include <stdint.h>

#define NN   100000
#define EE   1600000
#define FIN  128
#define HD   256
#define NHID_ 512
#define NOUT_ 256
#define GG   256
#define NPART 98   // ceil(NN/1024)

__device__ __forceinline__ uint32_t smem_u32(const void* p) {
    uint32_t a;
    asm("{ .reg .u64 t; cvta.to.shared.u64 t, %1; cvt.u32.u64 %0, t; }" : "=r"(a) : "l"(p));
    return a;
}

// ---------------- scratch (no allocation allowed) ----------------
__device__ __align__(256) __half g_t16[(size_t)NN * HD];     // SpMM out / GEMM in
__device__ __align__(256) __half g_a16[(size_t)NN * HD];     // GEMM out / SpMM in (also x16)
__device__ __align__(256) __half g_wt[3][HD * HD];           // W^T fp16 per layer
__device__ int   g_deg[NN];
__device__ float g_dinv[NN];
__device__ int   g_rowoff[NN + 1];
__device__ int   g_cursor[NN];
__device__ int   g_col[EE];
__device__ float g_w[EE];
__device__ int   g_part[NPART];
__device__ int   g_poff[NPART];
__device__ int   g_gstart[GG + 1];
__device__ float g_pooled[GG * HD];
__device__ float g_o3[GG * HD];
__device__ float g_mlp1[GG * NHID_];

// ---------------- CSR construction ----------------
__global__ void zero_deg_kernel() {
    int i = blockIdx.x * blockDim.x + threadIdx.x;
    if (i < NN) g_deg[i] = 0;
}

__global__ void count_kernel(const int* __restrict__ dst) {
    int e = blockIdx.x * blockDim.x + threadIdx.x;
    if (e < EE) atomicAdd(&g_deg[dst[e]], 1);
}

__global__ void partial_kernel() {
    __shared__ int sh[1024];
    int i = blockIdx.x * 1024 + threadIdx.x;
    sh[threadIdx.x] = (i < NN) ? g_deg[i] : 0;
    __syncthreads();
    for (int off = 512; off > 0; off >>= 1) {
        if (threadIdx.x < off) sh[threadIdx.x] += sh[threadIdx.x + off];
        __syncthreads();
    }
    if (threadIdx.x == 0) g_part[blockIdx.x] = sh[0];
}

__global__ void scanpart_kernel() {
    __shared__ int sh[128];
    int tid = threadIdx.x;
    int v = (tid < NPART) ? g_part[tid] : 0;
    sh[tid] = v;
    __syncthreads();
    for (int off = 1; off < 128; off <<= 1) {
        int t = (tid >= off) ? sh[tid - off] : 0;
        __syncthreads();
        sh[tid] += t;
        __syncthreads();
    }
    if (tid < NPART) g_poff[tid] = sh[tid] - v;
    if (tid == 127) g_rowoff[NN] = sh[127];
}

__global__ void apply_kernel() {
    __shared__ int sh[1024];
    int tid = threadIdx.x;
    int i = blockIdx.x * 1024 + tid;
    int v = (i < NN) ? g_deg[i] : 0;
    sh[tid] = v;
    __syncthreads();
    for (int off = 1; off < 1024; off <<= 1) {
        int t = (tid >= off) ? sh[tid - off] : 0;
        __syncthreads();
        sh[tid] += t;
        __syncthreads();
    }
    if (i < NN) {
        int excl = sh[tid] - v + g_poff[blockIdx.x];
        g_rowoff[i] = excl;
        g_cursor[i] = excl;
    }
}

__global__ void dinv_kernel() {
    int i = blockIdx.x * blockDim.x + threadIdx.x;
    if (i < NN) g_dinv[i] = rsqrtf(1.0f + (float)g_deg[i]);
}

__global__ void scatter_kernel(const int* __restrict__ src, const int* __restrict__ dst) {
    int e = blockIdx.x * blockDim.x + threadIdx.x;
    if (e < EE) {
        int s = src[e];
        int p = atomicAdd(&g_cursor[dst[e]], 1);
        g_col[p] = s;
        g_w[p] = g_dinv[s];
    }
}

// ---------------- converts ----------------
__global__ void convX_kernel(const float* __restrict__ A,
                             __half* __restrict__ A16, size_t n) {
    size_t i = (size_t)(blockIdx.x) * blockDim.x + threadIdx.x;
    if (i * 2 >= n) return;
    float2 a = *(const float2*)(A + i * 2);
    __half2 hp;
    hp.x = __float2half_rn(a.x);
    hp.y = __float2half_rn(a.y);
    *(__half2*)(A16 + i * 2) = hp;
}

// W [K,N] fp32 -> Wt [N,K] fp16 (transposed)
__global__ void splitW_kernel(const float* __restrict__ W,
                              __half* __restrict__ Wt, int K, int N) {
    int idx = blockIdx.x * blockDim.x + threadIdx.x;
    if (idx >= K * N) return;
    int k = idx / N, n = idx % N;
    Wt[(size_t)n * K + k] = __float2half_rn(W[idx]);
}

// ---------------- fp16 mma.sync GEMM: C16 = relu?(A16 @ Wt^T + bias) ----------------
// BM=128, BN=256, BK=32, 512 threads (16 warps, warp tile 32x64), 5-stage cp.async.
#define STAGE_BYTES 30720   // A: 128*80 = 10240 ; B: 256*80 = 20480
#define NSTAGE 5
template <bool RELU>
__global__ void __launch_bounds__(512, 1)
gemm_mma2_kernel(const __half* __restrict__ A16,
                 const __half* __restrict__ B16,
                 const float* __restrict__ bias,
                 __half* __restrict__ C16, int M, int K)
{
    extern __shared__ char smem_raw[];
    const uint32_t base = smem_u32(smem_raw);

    const int tid  = threadIdx.x;
    const int wid  = tid >> 5;
    const int lane = tid & 31;
    const int m0 = blockIdx.x * 128;
    const int wm = (wid & 3) * 32;     // 0..96
    const int wn = (wid >> 2) * 64;    // 0..192

    float acc[2][8][4];
#pragma unroll
    for (int i = 0; i < 2; i++)
#pragma unroll
        for (int j = 0; j < 8; j++)
#pragma unroll
            for (int q = 0; q < 4; q++) acc[i][j][q] = 0.0f;

    const int NKB = K / 32;

    auto load_stage = [&](int kb, int s) {
        const uint32_t sb = base + (uint32_t)s * STAGE_BYTES;
        int k0 = kb * 32;
        {   // A: 512 x 16B
            int row = tid >> 2, seg = tid & 3;
            const __half* gp = A16 + (size_t)(m0 + row) * K + k0 + seg * 8;
            uint32_t d = sb + row * 80 + seg * 16;
            uint32_t sz = (m0 + row < M) ? 16u : 0u;
            asm volatile("cp.async.cg.shared.global [%0], [%1], 16, %2;"
                         :: "r"(d), "l"(gp), "r"(sz) : "memory");
        }
#pragma unroll
        for (int it = 0; it < 2; it++) {   // B: 1024 x 16B
            int u = tid + it * 512;
            int row = u >> 2, seg = u & 3;
            const __half* gp = B16 + (size_t)row * K + k0 + seg * 8;
            uint32_t d = sb + 10240 + row * 80 + seg * 16;
            asm volatile("cp.async.cg.shared.global [%0], [%1], 16;"
                         :: "r"(d), "l"(gp) : "memory");
        }
        asm volatile("cp.async.commit_group;" ::: "memory");
    };

    for (int s = 0; s < 4 && s < NKB; s++) load_stage(s, s);

    const int tg = lane >> 3;   // 0..3
    const int tr = lane & 7;    // 0..7

    for (int kb = 0; kb < NKB; kb++) {
        int rem = NKB - 1 - kb;
        if (rem >= 3)      asm volatile("cp.async.wait_group 3;" ::: "memory");
        else if (rem == 2) asm volatile("cp.async.wait_group 2;" ::: "memory");
        else if (rem == 1) asm volatile("cp.async.wait_group 1;" ::: "memory");
        else               asm volatile("cp.async.wait_group 0;" ::: "memory");
        __syncthreads();
        if (kb + 4 < NKB) load_stage(kb + 4, (kb + 4) % NSTAGE);

        const int s = kb % NSTAGE;
        const uint32_t Ab = base + (uint32_t)s * STAGE_BYTES;
        const uint32_t Bb = Ab + 10240;

#pragma unroll
        for (int ks = 0; ks < 2; ks++) {
            int kb16 = ks * 16;
            uint32_t a[2][4];
#pragma unroll
            for (int mi = 0; mi < 2; mi++) {
                uint32_t addr = Ab + (wm + mi * 16 + tr + (tg & 1) * 8) * 80
                                   + (kb16 + (tg >> 1) * 8) * 2;
                asm volatile("ldmatrix.sync.aligned.m8n8.x4.shared.b16 {%0,%1,%2,%3}, [%4];"
                             : "=r"(a[mi][0]), "=r"(a[mi][1]), "=r"(a[mi][2]), "=r"(a[mi][3])
                             : "r"(addr));
            }
#pragma unroll
            for (int np = 0; np < 4; np++) {
                uint32_t b[4];
                uint32_t addr = Bb + (wn + np * 16 + (tg >> 1) * 8 + tr) * 80
                                   + (kb16 + (tg & 1) * 8) * 2;
                asm volatile("ldmatrix.sync.aligned.m8n8.x4.shared.b16 {%0,%1,%2,%3}, [%4];"
                             : "=r"(b[0]), "=r"(b[1]), "=r"(b[2]), "=r"(b[3])
                             : "r"(addr));
#pragma unroll
                for (int mi = 0; mi < 2; mi++) {
#pragma unroll
                    for (int hh = 0; hh < 2; hh++) {
                        float* c = acc[mi][np * 2 + hh];
                        asm volatile(
                            "mma.sync.aligned.m16n8k16.row.col.f32.f16.f16.f32 "
                            "{%0,%1,%2,%3}, {%4,%5,%6,%7}, {%8,%9}, {%0,%1,%2,%3};"
                            : "+f"(c[0]), "+f"(c[1]), "+f"(c[2]), "+f"(c[3])
                            : "r"(a[mi][0]), "r"(a[mi][1]), "r"(a[mi][2]), "r"(a[mi][3]),
                              "r"(b[hh * 2]), "r"(b[hh * 2 + 1]));
                    }
                }
            }
        }
    }

    // epilogue: bias (+relu), fp16 output
#pragma unroll
    for (int mi = 0; mi < 2; mi++) {
        int r0 = m0 + wm + mi * 16 + (lane >> 2);
#pragma unroll
        for (int ni = 0; ni < 8; ni++) {
            int cc = wn + ni * 8 + (lane & 3) * 2;
            float bx = bias[cc], by = bias[cc + 1];
            float* c = acc[mi][ni];
            float v0 = c[0] + bx, v1 = c[1] + by;
            float v2 = c[2] + bx, v3 = c[3] + by;
            if (RELU) {
                v0 = fmaxf(v0, 0.f); v1 = fmaxf(v1, 0.f);
                v2 = fmaxf(v2, 0.f); v3 = fmaxf(v3, 0.f);
            }
            if (r0 < M) {
                __half2 v; v.x = __float2half_rn(v0); v.y = __float2half_rn(v1);
                *(__half2*)(C16 + (size_t)r0 * 256 + cc) = v;
            }
            if (r0 + 8 < M) {
                __half2 v; v.x = __float2half_rn(v2); v.y = __float2half_rn(v3);
                *(__half2*)(C16 + (size_t)(r0 + 8) * 256 + cc) = v;
            }
        }
    }
}

// ---------------- small fp32 GEMM (head): C = relu?(A@B + bias) ----------------
// BM=BN=64, BK=16, 256 threads, 4x4 per thread. M,N,K multiples of 16/64.
template <bool RELU>
__global__ void __launch_bounds__(256)
gemm64_kernel(const float* __restrict__ A, const float* __restrict__ B,
              const float* __restrict__ bias, float* __restrict__ C,
              int M, int K, int N) {
    __shared__ float As[16][68];
    __shared__ float Bs[16][68];
    const int tid = threadIdx.x;
    const int m0 = blockIdx.y * 64;
    const int n0 = blockIdx.x * 64;
    const int ty = tid >> 4;    // 0..15
    const int tx = tid & 15;    // 0..15

    const int ar = tid >> 2;          // 0..63 (A row)
    const int ac = (tid & 3) * 4;     // A col group
    const int br = tid >> 4;          // 0..15 (B row)
    const int bc = (tid & 15) * 4;    // B col group

    float acc[4][4];
#pragma unroll
    for (int i = 0; i < 4; i++)
#pragma unroll
        for (int j = 0; j < 4; j++) acc[i][j] = 0.0f;

    for (int k0 = 0; k0 < K; k0 += 16) {
        float4 av = *(const float4*)(A + (size_t)(m0 + ar) * K + k0 + ac);
        As[ac + 0][ar] = av.x;
        As[ac + 1][ar] = av.y;
        As[ac + 2][ar] = av.z;
        As[ac + 3][ar] = av.w;
        float4 bv = *(const float4*)(B + (size_t)(k0 + br) * N + n0 + bc);
        *(float4*)&Bs[br][bc] = bv;
        __syncthreads();

#pragma unroll
        for (int kk = 0; kk < 16; kk++) {
            float ar4[4], br4[4];
            float4 a4 = *(const float4*)&As[kk][ty * 4];
            float4 b4 = *(const float4*)&Bs[kk][tx * 4];
            ar4[0] = a4.x; ar4[1] = a4.y; ar4[2] = a4.z; ar4[3] = a4.w;
            br4[0] = b4.x; br4[1] = b4.y; br4[2] = b4.z; br4[3] = b4.w;
#pragma unroll
            for (int i = 0; i < 4; i++)
#pragma unroll
                for (int j = 0; j < 4; j++)
                    acc[i][j] = fmaf(ar4[i], br4[j], acc[i][j]);
        }
        __syncthreads();
    }

#pragma unroll
    for (int i = 0; i < 4; i++) {
        int row = m0 + ty * 4 + i;
#pragma unroll
        for (int j = 0; j < 4; j++) {
            int col = n0 + tx * 4 + j;
            float v = acc[i][j] + bias[col];
            if (RELU) v = fmaxf(v, 0.0f);
            C[(size_t)row * N + col] = v;
        }
    }
}

// ---------------- SpMM over fp16 rows + self-loop (no bias/relu), fp16 out ----------------
// warp per node; WIDTH=256: lane owns uint4 (8 ch). WIDTH=128: lane owns uint2 (4 ch).
__global__ void __launch_bounds__(256)
spmm16_256_kernel(const __half* __restrict__ Hin, __half* __restrict__ Hout) {
    int node = blockIdx.x * 8 + (threadIdx.x >> 5);
    if (node >= NN) return;
    int lane = threadIdx.x & 31;
    float di = g_dinv[node];
    const uint4* hp = (const uint4*)Hin;

    float acc[8];
    {
        float w0 = di * di;
        uint4 v = hp[(size_t)node * 32 + lane];
        float2 f0 = __half22float2(*(__half2*)&v.x);
        float2 f1 = __half22float2(*(__half2*)&v.y);
        float2 f2 = __half22float2(*(__half2*)&v.z);
        float2 f3 = __half22float2(*(__half2*)&v.w);
        acc[0] = f0.x * w0; acc[1] = f0.y * w0;
        acc[2] = f1.x * w0; acc[3] = f1.y * w0;
        acc[4] = f2.x * w0; acc[5] = f2.y * w0;
        acc[6] = f3.x * w0; acc[7] = f3.y * w0;
    }

    int s = g_rowoff[node];
    int e = g_rowoff[node + 1];
    int p = s;

#define ACC_ROW8(vv, ww) do { \
        float2 f0 = __half22float2(*(__half2*)&(vv).x); \
        float2 f1 = __half22float2(*(__half2*)&(vv).y); \
        float2 f2 = __half22float2(*(__half2*)&(vv).z); \
        float2 f3 = __half22float2(*(__half2*)&(vv).w); \
        acc[0] = fmaf((ww), f0.x, acc[0]); acc[1] = fmaf((ww), f0.y, acc[1]); \
        acc[2] = fmaf((ww), f1.x, acc[2]); acc[3] = fmaf((ww), f1.y, acc[3]); \
        acc[4] = fmaf((ww), f2.x, acc[4]); acc[5] = fmaf((ww), f2.y, acc[5]); \
        acc[6] = fmaf((ww), f3.x, acc[6]); acc[7] = fmaf((ww), f3.y, acc[7]); \
    } while (0)

    for (; p + 4 <= e; p += 4) {
        int j0 = g_col[p], j1 = g_col[p + 1], j2 = g_col[p + 2], j3 = g_col[p + 3];
        float w0 = di * g_w[p], w1 = di * g_w[p + 1];
        float w2 = di * g_w[p + 2], w3 = di * g_w[p + 3];
        uint4 v0 = hp[(size_t)j0 * 32 + lane];
        uint4 v1 = hp[(size_t)j1 * 32 + lane];
        uint4 v2 = hp[(size_t)j2 * 32 + lane];
        uint4 v3 = hp[(size_t)j3 * 32 + lane];
        ACC_ROW8(v0, w0); ACC_ROW8(v1, w1); ACC_ROW8(v2, w2); ACC_ROW8(v3, w3);
    }
    for (; p < e; p++) {
        int j0 = g_col[p];
        float w0 = di * g_w[p];
        uint4 v0 = hp[(size_t)j0 * 32 + lane];
        ACC_ROW8(v0, w0);
    }
#undef ACC_ROW8

    uint4 o;
    __half2 t;
    t.x = __float2half_rn(acc[0]); t.y = __float2half_rn(acc[1]); o.x = *(uint32_t*)&t;
    t.x = __float2half_rn(acc[2]); t.y = __float2half_rn(acc[3]); o.y = *(uint32_t*)&t;
    t.x = __float2half_rn(acc[4]); t.y = __float2half_rn(acc[5]); o.z = *(uint32_t*)&t;
    t.x = __float2half_rn(acc[6]); t.y = __float2half_rn(acc[7]); o.w = *(uint32_t*)&t;
    ((uint4*)Hout)[(size_t)node * 32 + lane] = o;
}

__global__ void __launch_bounds__(256)
spmm16_128_kernel(const __half* __restrict__ Hin, __half* __restrict__ Hout) {
    int node = blockIdx.x * 8 + (threadIdx.x >> 5);
    if (node >= NN) return;
    int lane = threadIdx.x & 31;
    float di = g_dinv[node];
    const uint2* hp = (const uint2*)Hin;   // 4 halves per uint2; 32 per 128-wide row

    float acc[4];
    {
        float w0 = di * di;
        uint2 v = hp[(size_t)node * 32 + lane];
        float2 f0 = __half22float2(*(__half2*)&v.x);
        float2 f1 = __half22float2(*(__half2*)&v.y);
        acc[0] = f0.x * w0; acc[1] = f0.y * w0;
        acc[2] = f1.x * w0; acc[3] = f1.y * w0;
    }

    int s = g_rowoff[node];
    int e = g_rowoff[node + 1];
    int p = s;

#define ACC_ROW4(vv, ww) do { \
        float2 f0 = __half22float2(*(__half2*)&(vv).x); \
        float2 f1 = __half22float2(*(__half2*)&(vv).y); \
        acc[0] = fmaf((ww), f0.x, acc[0]); acc[1] = fmaf((ww), f0.y, acc[1]); \
        acc[2] = fmaf((ww), f1.x, acc[2]); acc[3] = fmaf((ww), f1.y, acc[3]); \
    } while (0)

    for (; p + 4 <= e; p += 4) {
        int j0 = g_col[p], j1 = g_col[p + 1], j2 = g_col[p + 2], j3 = g_col[p + 3];
        float w0 = di * g_w[p], w1 = di * g_w[p + 1];
        float w2 = di * g_w[p + 2], w3 = di * g_w[p + 3];
        uint2 v0 = hp[(size_t)j0 * 32 + lane];
        uint2 v1 = hp[(size_t)j1 * 32 + lane];
        uint2 v2 = hp[(size_t)j2 * 32 + lane];
        uint2 v3 = hp[(size_t)j3 * 32 + lane];
        ACC_ROW4(v0, w0); ACC_ROW4(v1, w1); ACC_ROW4(v2, w2); ACC_ROW4(v3, w3);
    }
    for (; p < e; p++) {
        int j0 = g_col[p];
        float w0 = di * g_w[p];
        uint2 v0 = hp[(size_t)j0 * 32 + lane];
        ACC_ROW4(v0, w0);
    }
#undef ACC_ROW4

    uint2 o;
    __half2 t;
    t.x = __float2half_rn(acc[0]); t.y = __float2half_rn(acc[1]); o.x = *(uint32_t*)&t;
    t.x = __float2half_rn(acc[2]); t.y = __float2half_rn(acc[3]); o.y = *(uint32_t*)&t;
    ((uint2*)Hout)[(size_t)node * 32 + lane] = o;
}

// ---------------- pooling (batch is sorted), fp16 input ----------------
__global__ void bounds_kernel(const int* __restrict__ batch) {
    int i = blockIdx.x * blockDim.x + threadIdx.x;
    if (i >= NN) return;
    int b = batch[i];
    int prev = (i == 0) ? -1 : batch[i - 1];
    for (int g = prev + 1; g <= b; g++) g_gstart[g] = i;
    if (i == NN - 1)
        for (int g = b + 1; g <= GG; g++) g_gstart[g] = NN;
}

__global__ void pool16_kernel(const __half* __restrict__ H) {
    int g = blockIdx.x;
    int c = threadIdx.x;
    int s = g_gstart[g];
    int e = g_gstart[g + 1];
    float acc = 0.0f;
    for (int i = s; i < e; i++) acc += __half2float(H[(size_t)i * HD + c]);
    float cnt = (float)(e - s);
    if (cnt < 1.0f) cnt = 1.0f;
    g_pooled[g * HD + c] = acc / cnt;
}

// ---------------- launch ----------------
extern "C" void kernel_launch(void* const* d_in, const int* in_sizes, int n_in,
                              void* d_out, int out_size) {
    const float* x     = (const float*)d_in[0];
    const int*   src   = (const int*)d_in[1];
    const int*   dst   = (const int*)d_in[2];
    const int*   batch = (const int*)d_in[3];
    const float* W1 = (const float*)d_in[4];
    const float* b1 = (const float*)d_in[5];
    const float* W2 = (const float*)d_in[6];
    const float* b2 = (const float*)d_in[7];
    const float* W3 = (const float*)d_in[8];
    const float* b3 = (const float*)d_in[9];
    const float* Wm1 = (const float*)d_in[10];
    const float* bm1 = (const float*)d_in[11];
    const float* Wm2 = (const float*)d_in[12];
    const float* bm2 = (const float*)d_in[13];
    float* out = (float*)d_out;

    float *pooled, *o3, *mlp1;
    __half *t16, *a16, *wt;
    cudaGetSymbolAddress((void**)&t16, g_t16);
    cudaGetSymbolAddress((void**)&a16, g_a16);
    cudaGetSymbolAddress((void**)&pooled, g_pooled);
    cudaGetSymbolAddress((void**)&o3, g_o3);
    cudaGetSymbolAddress((void**)&mlp1, g_mlp1);
    cudaGetSymbolAddress((void**)&wt, g_wt);

    const int GSMEM = NSTAGE * STAGE_BYTES;   // 153600
    cudaFuncSetAttribute(gemm_mma2_kernel<true>,
                         cudaFuncAttributeMaxDynamicSharedMemorySize, GSMEM);

    const int TB = 256;
    const size_t WSTRIDE = (size_t)HD * HD;

    const int gemm_grid = (NN + 127) / 128;   // 782
    const int spmm_grid = (NN + 7) / 8;

    // ----- prep: converts + CSR -----
    convX_kernel<<<(int)(((size_t)NN * FIN / 2 + TB - 1) / TB), TB>>>(x, a16, (size_t)NN * FIN);
    splitW_kernel<<<(FIN * HD + TB - 1) / TB, TB>>>(W1, wt + 0 * WSTRIDE, FIN, HD);
    splitW_kernel<<<(HD * HD + TB - 1) / TB, TB>>>(W2, wt + 1 * WSTRIDE, HD, HD);
    zero_deg_kernel<<<(NN + TB - 1) / TB, TB>>>();
    count_kernel<<<(EE + TB - 1) / TB, TB>>>(dst);
    partial_kernel<<<NPART, 1024>>>();
    scanpart_kernel<<<1, 128>>>();
    apply_kernel<<<NPART, 1024>>>();
    dinv_kernel<<<(NN + TB - 1) / TB, TB>>>();
    scatter_kernel<<<(EE + TB - 1) / TB, TB>>>(src, dst);

    // ----- layer 1: S1 = Agg(x16) [N,128]; H1 = relu(S1@W1 + b1) -----
    spmm16_128_kernel<<<spmm_grid, 256>>>(a16, t16);
    gemm_mma2_kernel<true><<<gemm_grid, 512, GSMEM>>>(t16, wt + 0 * WSTRIDE, b1, a16, NN, FIN);
    // ----- layer 2 -----
    spmm16_256_kernel<<<spmm_grid, 256>>>(a16, t16);
    gemm_mma2_kernel<true><<<gemm_grid, 512, GSMEM>>>(t16, wt + 1 * WSTRIDE, b2, a16, NN, HD);
    // ----- layer 3: S3 = Agg(H2); pool; then tiny GEMM with W3 -----
    spmm16_256_kernel<<<spmm_grid, 256>>>(a16, t16);
    bounds_kernel<<<(NN + TB - 1) / TB, TB>>>(batch);
    pool16_kernel<<<GG, HD>>>(t16);

    // ----- head (fp32): o3 = pooled@W3 + b3 ; mlp1 = relu(o3@Wm1+bm1) ; out = mlp1@Wm2+bm2 -----
    dim3 g3(HD / 64, GG / 64);
    gemm64_kernel<false><<<g3, 256>>>(pooled, W3, b3, o3, GG, HD, HD);
    dim3 gm1(NHID_ / 64, GG / 64);
    gemm64_kernel<true><<<gm1, 256>>>(o3, Wm1, bm1, mlp1, GG, HD, NHID_);
    dim3 gm2(NOUT_ / 64, GG / 64);
    gemm64_kernel<false><<<gm2, 256>>>(mlp1, Wm2, bm2, out, GG, NHID_, NOUT_);
}

// round 10
// speedup vs baseline: 4.4837x; 1.0563x over previous
#include <cuda_runtime.h>
#include <cuda_fp16.h>
#include <math.h>
#include <stdint.h>

#define NN   100000
#define EE   1600000
#define FIN  128
#define HD   256
#define NHID_ 512
#define NOUT_ 256
#define GG   256
#define NPART 98   // ceil(NN/1024)

__device__ __forceinline__ uint32_t smem_u32(const void* p) {
    uint32_t a;
    asm("{ .reg .u64 t; cvta.to.shared.u64 t, %1; cvt.u32.u64 %0, t; }" : "=r"(a) : "l"(p));
    return a;
}

// ---------------- scratch (no allocation allowed) ----------------
__device__ __align__(256) __half g_t16[(size_t)NN * HD];     // SpMM out / GEMM in
__device__ __align__(256) __half g_a16[(size_t)NN * HD];     // GEMM out / SpMM in (also x16)
__device__ __align__(256) __half g_wt[2][HD * HD];           // W^T fp16 (layers 1,2)
__device__ int   g_deg[NN];
__device__ float g_dinv[NN];
__device__ int   g_rowoff[NN + 1];
__device__ int   g_cursor[NN];
__device__ int   g_col[EE];
__device__ float g_w[EE];
__device__ int   g_part[NPART];
__device__ int   g_poff[NPART];
__device__ int   g_gstart[GG + 1];
__device__ float g_pooled[GG * HD];
__device__ float g_o3[GG * HD];
__device__ float g_mlp1[GG * NHID_];

// ---------------- CSR construction ----------------
__global__ void zero_deg_kernel() {
    int i = blockIdx.x * blockDim.x + threadIdx.x;
    if (i < NN) g_deg[i] = 0;
}

__global__ void count_kernel(const int* __restrict__ dst) {
    int e = blockIdx.x * blockDim.x + threadIdx.x;
    if (e < EE) atomicAdd(&g_deg[dst[e]], 1);
}

__global__ void partial_kernel() {
    __shared__ int sh[1024];
    int i = blockIdx.x * 1024 + threadIdx.x;
    sh[threadIdx.x] = (i < NN) ? g_deg[i] : 0;
    __syncthreads();
    for (int off = 512; off > 0; off >>= 1) {
        if (threadIdx.x < off) sh[threadIdx.x] += sh[threadIdx.x + off];
        __syncthreads();
    }
    if (threadIdx.x == 0) g_part[blockIdx.x] = sh[0];
}

__global__ void scanpart_kernel() {
    __shared__ int sh[128];
    int tid = threadIdx.x;
    int v = (tid < NPART) ? g_part[tid] : 0;
    sh[tid] = v;
    __syncthreads();
    for (int off = 1; off < 128; off <<= 1) {
        int t = (tid >= off) ? sh[tid - off] : 0;
        __syncthreads();
        sh[tid] += t;
        __syncthreads();
    }
    if (tid < NPART) g_poff[tid] = sh[tid] - v;
    if (tid == 127) g_rowoff[NN] = sh[127];
}

// per-block local scan + global offset -> rowoff/cursor ; also dinv (fused)
__global__ void apply_kernel() {
    __shared__ int sh[1024];
    int tid = threadIdx.x;
    int i = blockIdx.x * 1024 + tid;
    int v = (i < NN) ? g_deg[i] : 0;
    sh[tid] = v;
    __syncthreads();
    for (int off = 1; off < 1024; off <<= 1) {
        int t = (tid >= off) ? sh[tid - off] : 0;
        __syncthreads();
        sh[tid] += t;
        __syncthreads();
    }
    if (i < NN) {
        int excl = sh[tid] - v + g_poff[blockIdx.x];
        g_rowoff[i] = excl;
        g_cursor[i] = excl;
        g_dinv[i] = rsqrtf(1.0f + (float)v);
    }
}

__global__ void scatter_kernel(const int* __restrict__ src, const int* __restrict__ dst) {
    int e = blockIdx.x * blockDim.x + threadIdx.x;
    if (e < EE) {
        int s = src[e];
        int p = atomicAdd(&g_cursor[dst[e]], 1);
        g_col[p] = s;
        g_w[p] = g_dinv[s];
    }
}

// ---------------- converts ----------------
__global__ void convX_kernel(const float* __restrict__ A,
                             __half* __restrict__ A16, size_t n) {
    size_t i = (size_t)(blockIdx.x) * blockDim.x + threadIdx.x;
    if (i * 2 >= n) return;
    float2 a = *(const float2*)(A + i * 2);
    __half2 hp;
    hp.x = __float2half_rn(a.x);
    hp.y = __float2half_rn(a.y);
    *(__half2*)(A16 + i * 2) = hp;
}

// W [K,N] fp32 -> Wt [N,K] fp16 (transposed)
__global__ void splitW_kernel(const float* __restrict__ W,
                              __half* __restrict__ Wt, int K, int N) {
    int idx = blockIdx.x * blockDim.x + threadIdx.x;
    if (idx >= K * N) return;
    int k = idx / N, n = idx % N;
    Wt[(size_t)n * K + k] = __float2half_rn(W[idx]);
}

// ---------------- fp16 mma.sync GEMM: C16 = relu(A16 @ Wt^T + bias) ----------------
// BM=128, BN=128, BK=32, 256 threads (8 warps, warp tile 32x64), 5-stage cp.async,
// 2 CTAs/SM for latency hiding.
#define STAGE_BYTES 20480   // A: 128*80 = 10240 ; B: 128*80 = 10240
#define NSTAGE 5
__global__ void __launch_bounds__(256, 2)
gemm_mma2_kernel(const __half* __restrict__ A16,
                 const __half* __restrict__ B16,
                 const float* __restrict__ bias,
                 __half* __restrict__ C16, int M, int K)
{
    extern __shared__ char smem_raw[];
    const uint32_t base = smem_u32(smem_raw);

    const int tid  = threadIdx.x;
    const int wid  = tid >> 5;
    const int lane = tid & 31;
    const int m0 = blockIdx.y * 128;
    const int n0 = blockIdx.x * 128;
    const int wm = (wid & 3) * 32;     // 0..96
    const int wn = (wid >> 2) * 64;    // 0,64

    float acc[2][8][4];
#pragma unroll
    for (int i = 0; i < 2; i++)
#pragma unroll
        for (int j = 0; j < 8; j++)
#pragma unroll
            for (int q = 0; q < 4; q++) acc[i][j][q] = 0.0f;

    const int NKB = K / 32;

    auto load_stage = [&](int kb, int s) {
        const uint32_t sb = base + (uint32_t)s * STAGE_BYTES;
        int k0 = kb * 32;
#pragma unroll
        for (int it = 0; it < 2; it++) {   // A: 512 x 16B over 256 threads
            int u = tid + it * 256;
            int row = u >> 2, seg = u & 3;
            const __half* gp = A16 + (size_t)(m0 + row) * K + k0 + seg * 8;
            uint32_t d = sb + row * 80 + seg * 16;
            uint32_t sz = (m0 + row < M) ? 16u : 0u;
            asm volatile("cp.async.cg.shared.global [%0], [%1], 16, %2;"
                         :: "r"(d), "l"(gp), "r"(sz) : "memory");
        }
#pragma unroll
        for (int it = 0; it < 2; it++) {   // B: 512 x 16B
            int u = tid + it * 256;
            int row = u >> 2, seg = u & 3;
            const __half* gp = B16 + (size_t)(n0 + row) * K + k0 + seg * 8;
            uint32_t d = sb + 10240 + row * 80 + seg * 16;
            asm volatile("cp.async.cg.shared.global [%0], [%1], 16;"
                         :: "r"(d), "l"(gp) : "memory");
        }
        asm volatile("cp.async.commit_group;" ::: "memory");
    };

    for (int s = 0; s < 4 && s < NKB; s++) load_stage(s, s);

    const int tg = lane >> 3;   // 0..3
    const int tr = lane & 7;    // 0..7

    for (int kb = 0; kb < NKB; kb++) {
        int rem = NKB - 1 - kb;
        if (rem >= 3)      asm volatile("cp.async.wait_group 3;" ::: "memory");
        else if (rem == 2) asm volatile("cp.async.wait_group 2;" ::: "memory");
        else if (rem == 1) asm volatile("cp.async.wait_group 1;" ::: "memory");
        else               asm volatile("cp.async.wait_group 0;" ::: "memory");
        __syncthreads();
        if (kb + 4 < NKB) load_stage(kb + 4, (kb + 4) % NSTAGE);

        const int s = kb % NSTAGE;
        const uint32_t Ab = base + (uint32_t)s * STAGE_BYTES;
        const uint32_t Bb = Ab + 10240;

#pragma unroll
        for (int ks = 0; ks < 2; ks++) {
            int kb16 = ks * 16;
            uint32_t a[2][4];
#pragma unroll
            for (int mi = 0; mi < 2; mi++) {
                uint32_t addr = Ab + (wm + mi * 16 + tr + (tg & 1) * 8) * 80
                                   + (kb16 + (tg >> 1) * 8) * 2;
                asm volatile("ldmatrix.sync.aligned.m8n8.x4.shared.b16 {%0,%1,%2,%3}, [%4];"
                             : "=r"(a[mi][0]), "=r"(a[mi][1]), "=r"(a[mi][2]), "=r"(a[mi][3])
                             : "r"(addr));
            }
#pragma unroll
            for (int np = 0; np < 4; np++) {
                uint32_t b[4];
                uint32_t addr = Bb + (wn + np * 16 + (tg >> 1) * 8 + tr) * 80
                                   + (kb16 + (tg & 1) * 8) * 2;
                asm volatile("ldmatrix.sync.aligned.m8n8.x4.shared.b16 {%0,%1,%2,%3}, [%4];"
                             : "=r"(b[0]), "=r"(b[1]), "=r"(b[2]), "=r"(b[3])
                             : "r"(addr));
#pragma unroll
                for (int mi = 0; mi < 2; mi++) {
#pragma unroll
                    for (int hh = 0; hh < 2; hh++) {
                        float* c = acc[mi][np * 2 + hh];
                        asm volatile(
                            "mma.sync.aligned.m16n8k16.row.col.f32.f16.f16.f32 "
                            "{%0,%1,%2,%3}, {%4,%5,%6,%7}, {%8,%9}, {%0,%1,%2,%3};"
                            : "+f"(c[0]), "+f"(c[1]), "+f"(c[2]), "+f"(c[3])
                            : "r"(a[mi][0]), "r"(a[mi][1]), "r"(a[mi][2]), "r"(a[mi][3]),
                              "r"(b[hh * 2]), "r"(b[hh * 2 + 1]));
                    }
                }
            }
        }
    }

    // epilogue: bias + relu, fp16 output
#pragma unroll
    for (int mi = 0; mi < 2; mi++) {
        int r0 = m0 + wm + mi * 16 + (lane >> 2);
#pragma unroll
        for (int ni = 0; ni < 8; ni++) {
            int cc = n0 + wn + ni * 8 + (lane & 3) * 2;
            float bx = bias[cc], by = bias[cc + 1];
            float* c = acc[mi][ni];
            float v0 = fmaxf(c[0] + bx, 0.f), v1 = fmaxf(c[1] + by, 0.f);
            float v2 = fmaxf(c[2] + bx, 0.f), v3 = fmaxf(c[3] + by, 0.f);
            if (r0 < M) {
                __half2 v; v.x = __float2half_rn(v0); v.y = __float2half_rn(v1);
                *(__half2*)(C16 + (size_t)r0 * 256 + cc) = v;
            }
            if (r0 + 8 < M) {
                __half2 v; v.x = __float2half_rn(v2); v.y = __float2half_rn(v3);
                *(__half2*)(C16 + (size_t)(r0 + 8) * 256 + cc) = v;
            }
        }
    }
}

// ---------------- small fp32 GEMM (head): C = relu?(A@B + bias) ----------------
template <bool RELU>
__global__ void __launch_bounds__(256)
gemm64_kernel(const float* __restrict__ A, const float* __restrict__ B,
              const float* __restrict__ bias, float* __restrict__ C,
              int M, int K, int N) {
    __shared__ float As[16][68];
    __shared__ float Bs[16][68];
    const int tid = threadIdx.x;
    const int m0 = blockIdx.y * 64;
    const int n0 = blockIdx.x * 64;
    const int ty = tid >> 4;
    const int tx = tid & 15;

    const int ar = tid >> 2;
    const int ac = (tid & 3) * 4;
    const int br = tid >> 4;
    const int bc = (tid & 15) * 4;

    float acc[4][4];
#pragma unroll
    for (int i = 0; i < 4; i++)
#pragma unroll
        for (int j = 0; j < 4; j++) acc[i][j] = 0.0f;

    for (int k0 = 0; k0 < K; k0 += 16) {
        float4 av = *(const float4*)(A + (size_t)(m0 + ar) * K + k0 + ac);
        As[ac + 0][ar] = av.x;
        As[ac + 1][ar] = av.y;
        As[ac + 2][ar] = av.z;
        As[ac + 3][ar] = av.w;
        float4 bv = *(const float4*)(B + (size_t)(k0 + br) * N + n0 + bc);
        *(float4*)&Bs[br][bc] = bv;
        __syncthreads();

#pragma unroll
        for (int kk = 0; kk < 16; kk++) {
            float ar4[4], br4[4];
            float4 a4 = *(const float4*)&As[kk][ty * 4];
            float4 b4 = *(const float4*)&Bs[kk][tx * 4];
            ar4[0] = a4.x; ar4[1] = a4.y; ar4[2] = a4.z; ar4[3] = a4.w;
            br4[0] = b4.x; br4[1] = b4.y; br4[2] = b4.z; br4[3] = b4.w;
#pragma unroll
            for (int i = 0; i < 4; i++)
#pragma unroll
                for (int j = 0; j < 4; j++)
                    acc[i][j] = fmaf(ar4[i], br4[j], acc[i][j]);
        }
        __syncthreads();
    }

#pragma unroll
    for (int i = 0; i < 4; i++) {
        int row = m0 + ty * 4 + i;
#pragma unroll
        for (int j = 0; j < 4; j++) {
            int col = n0 + tx * 4 + j;
            float v = acc[i][j] + bias[col];
            if (RELU) v = fmaxf(v, 0.0f);
            C[(size_t)row * N + col] = v;
        }
    }
}

// ---------------- SpMM over fp16 rows + self-loop (no bias/relu), fp16 out ----------------
__global__ void __launch_bounds__(256)
spmm16_256_kernel(const __half* __restrict__ Hin, __half* __restrict__ Hout) {
    int node = blockIdx.x * 8 + (threadIdx.x >> 5);
    if (node >= NN) return;
    int lane = threadIdx.x & 31;
    float di = g_dinv[node];
    const uint4* hp = (const uint4*)Hin;

    float acc[8];
    {
        float w0 = di * di;
        uint4 v = hp[(size_t)node * 32 + lane];
        float2 f0 = __half22float2(*(__half2*)&v.x);
        float2 f1 = __half22float2(*(__half2*)&v.y);
        float2 f2 = __half22float2(*(__half2*)&v.z);
        float2 f3 = __half22float2(*(__half2*)&v.w);
        acc[0] = f0.x * w0; acc[1] = f0.y * w0;
        acc[2] = f1.x * w0; acc[3] = f1.y * w0;
        acc[4] = f2.x * w0; acc[5] = f2.y * w0;
        acc[6] = f3.x * w0; acc[7] = f3.y * w0;
    }

    int s = g_rowoff[node];
    int e = g_rowoff[node + 1];
    int p = s;

#define ACC_ROW8(vv, ww) do { \
        float2 f0 = __half22float2(*(__half2*)&(vv).x); \
        float2 f1 = __half22float2(*(__half2*)&(vv).y); \
        float2 f2 = __half22float2(*(__half2*)&(vv).z); \
        float2 f3 = __half22float2(*(__half2*)&(vv).w); \
        acc[0] = fmaf((ww), f0.x, acc[0]); acc[1] = fmaf((ww), f0.y, acc[1]); \
        acc[2] = fmaf((ww), f1.x, acc[2]); acc[3] = fmaf((ww), f1.y, acc[3]); \
        acc[4] = fmaf((ww), f2.x, acc[4]); acc[5] = fmaf((ww), f2.y, acc[5]); \
        acc[6] = fmaf((ww), f3.x, acc[6]); acc[7] = fmaf((ww), f3.y, acc[7]); \
    } while (0)

    for (; p + 8 <= e; p += 8) {
        int j0 = g_col[p], j1 = g_col[p + 1], j2 = g_col[p + 2], j3 = g_col[p + 3];
        int j4 = g_col[p + 4], j5 = g_col[p + 5], j6 = g_col[p + 6], j7 = g_col[p + 7];
        float w0 = di * g_w[p],     w1 = di * g_w[p + 1];
        float w2 = di * g_w[p + 2], w3 = di * g_w[p + 3];
        float w4 = di * g_w[p + 4], w5 = di * g_w[p + 5];
        float w6 = di * g_w[p + 6], w7 = di * g_w[p + 7];
        uint4 v0 = hp[(size_t)j0 * 32 + lane];
        uint4 v1 = hp[(size_t)j1 * 32 + lane];
        uint4 v2 = hp[(size_t)j2 * 32 + lane];
        uint4 v3 = hp[(size_t)j3 * 32 + lane];
        uint4 v4 = hp[(size_t)j4 * 32 + lane];
        uint4 v5 = hp[(size_t)j5 * 32 + lane];
        uint4 v6 = hp[(size_t)j6 * 32 + lane];
        uint4 v7 = hp[(size_t)j7 * 32 + lane];
        ACC_ROW8(v0, w0); ACC_ROW8(v1, w1); ACC_ROW8(v2, w2); ACC_ROW8(v3, w3);
        ACC_ROW8(v4, w4); ACC_ROW8(v5, w5); ACC_ROW8(v6, w6); ACC_ROW8(v7, w7);
    }
    for (; p < e; p++) {
        int j0 = g_col[p];
        float w0 = di * g_w[p];
        uint4 v0 = hp[(size_t)j0 * 32 + lane];
        ACC_ROW8(v0, w0);
    }
#undef ACC_ROW8

    uint4 o;
    __half2 t;
    t.x = __float2half_rn(acc[0]); t.y = __float2half_rn(acc[1]); o.x = *(uint32_t*)&t;
    t.x = __float2half_rn(acc[2]); t.y = __float2half_rn(acc[3]); o.y = *(uint32_t*)&t;
    t.x = __float2half_rn(acc[4]); t.y = __float2half_rn(acc[5]); o.z = *(uint32_t*)&t;
    t.x = __float2half_rn(acc[6]); t.y = __float2half_rn(acc[7]); o.w = *(uint32_t*)&t;
    ((uint4*)Hout)[(size_t)node * 32 + lane] = o;
}

__global__ void __launch_bounds__(256)
spmm16_128_kernel(const __half* __restrict__ Hin, __half* __restrict__ Hout) {
    int node = blockIdx.x * 8 + (threadIdx.x >> 5);
    if (node >= NN) return;
    int lane = threadIdx.x & 31;
    float di = g_dinv[node];
    const uint2* hp = (const uint2*)Hin;

    float acc[4];
    {
        float w0 = di * di;
        uint2 v = hp[(size_t)node * 32 + lane];
        float2 f0 = __half22float2(*(__half2*)&v.x);
        float2 f1 = __half22float2(*(__half2*)&v.y);
        acc[0] = f0.x * w0; acc[1] = f0.y * w0;
        acc[2] = f1.x * w0; acc[3] = f1.y * w0;
    }

    int s = g_rowoff[node];
    int e = g_rowoff[node + 1];
    int p = s;

#define ACC_ROW4(vv, ww) do { \
        float2 f0 = __half22float2(*(__half2*)&(vv).x); \
        float2 f1 = __half22float2(*(__half2*)&(vv).y); \
        acc[0] = fmaf((ww), f0.x, acc[0]); acc[1] = fmaf((ww), f0.y, acc[1]); \
        acc[2] = fmaf((ww), f1.x, acc[2]); acc[3] = fmaf((ww), f1.y, acc[3]); \
    } while (0)

    for (; p + 8 <= e; p += 8) {
        int j0 = g_col[p], j1 = g_col[p + 1], j2 = g_col[p + 2], j3 = g_col[p + 3];
        int j4 = g_col[p + 4], j5 = g_col[p + 5], j6 = g_col[p + 6], j7 = g_col[p + 7];
        float w0 = di * g_w[p],     w1 = di * g_w[p + 1];
        float w2 = di * g_w[p + 2], w3 = di * g_w[p + 3];
        float w4 = di * g_w[p + 4], w5 = di * g_w[p + 5];
        float w6 = di * g_w[p + 6], w7 = di * g_w[p + 7];
        uint2 v0 = hp[(size_t)j0 * 32 + lane];
        uint2 v1 = hp[(size_t)j1 * 32 + lane];
        uint2 v2 = hp[(size_t)j2 * 32 + lane];
        uint2 v3 = hp[(size_t)j3 * 32 + lane];
        uint2 v4 = hp[(size_t)j4 * 32 + lane];
        uint2 v5 = hp[(size_t)j5 * 32 + lane];
        uint2 v6 = hp[(size_t)j6 * 32 + lane];
        uint2 v7 = hp[(size_t)j7 * 32 + lane];
        ACC_ROW4(v0, w0); ACC_ROW4(v1, w1); ACC_ROW4(v2, w2); ACC_ROW4(v3, w3);
        ACC_ROW4(v4, w4); ACC_ROW4(v5, w5); ACC_ROW4(v6, w6); ACC_ROW4(v7, w7);
    }
    for (; p < e; p++) {
        int j0 = g_col[p];
        float w0 = di * g_w[p];
        uint2 v0 = hp[(size_t)j0 * 32 + lane];
        ACC_ROW4(v0, w0);
    }
#undef ACC_ROW4

    uint2 o;
    __half2 t;
    t.x = __float2half_rn(acc[0]); t.y = __float2half_rn(acc[1]); o.x = *(uint32_t*)&t;
    t.x = __float2half_rn(acc[2]); t.y = __float2half_rn(acc[3]); o.y = *(uint32_t*)&t;
    ((uint2*)Hout)[(size_t)node * 32 + lane] = o;
}

// ---------------- pooling (batch is sorted), fp16 input ----------------
__global__ void bounds_kernel(const int* __restrict__ batch) {
    int i = blockIdx.x * blockDim.x + threadIdx.x;
    if (i >= NN) return;
    int b = batch[i];
    int prev = (i == 0) ? -1 : batch[i - 1];
    for (int g = prev + 1; g <= b; g++) g_gstart[g] = i;
    if (i == NN - 1)
        for (int g = b + 1; g <= GG; g++) g_gstart[g] = NN;
}

__global__ void pool16_kernel(const __half* __restrict__ H) {
    int g = blockIdx.x;
    int c = threadIdx.x;
    int s = g_gstart[g];
    int e = g_gstart[g + 1];
    float acc = 0.0f;
    for (int i = s; i < e; i++) acc += __half2float(H[(size_t)i * HD + c]);
    float cnt = (float)(e - s);
    if (cnt < 1.0f) cnt = 1.0f;
    g_pooled[g * HD + c] = acc / cnt;
}

// ---------------- launch ----------------
extern "C" void kernel_launch(void* const* d_in, const int* in_sizes, int n_in,
                              void* d_out, int out_size) {
    const float* x     = (const float*)d_in[0];
    const int*   src   = (const int*)d_in[1];
    const int*   dst   = (const int*)d_in[2];
    const int*   batch = (const int*)d_in[3];
    const float* W1 = (const float*)d_in[4];
    const float* b1 = (const float*)d_in[5];
    const float* W2 = (const float*)d_in[6];
    const float* b2 = (const float*)d_in[7];
    const float* W3 = (const float*)d_in[8];
    const float* b3 = (const float*)d_in[9];
    const float* Wm1 = (const float*)d_in[10];
    const float* bm1 = (const float*)d_in[11];
    const float* Wm2 = (const float*)d_in[12];
    const float* bm2 = (const float*)d_in[13];
    float* out = (float*)d_out;

    float *pooled, *o3, *mlp1;
    __half *t16, *a16, *wt;
    cudaGetSymbolAddress((void**)&t16, g_t16);
    cudaGetSymbolAddress((void**)&a16, g_a16);
    cudaGetSymbolAddress((void**)&pooled, g_pooled);
    cudaGetSymbolAddress((void**)&o3, g_o3);
    cudaGetSymbolAddress((void**)&mlp1, g_mlp1);
    cudaGetSymbolAddress((void**)&wt, g_wt);

    const int GSMEM = NSTAGE * STAGE_BYTES;   // 102400
    cudaFuncSetAttribute(gemm_mma2_kernel,
                         cudaFuncAttributeMaxDynamicSharedMemorySize, GSMEM);

    const int TB = 256;
    const size_t WSTRIDE = (size_t)HD * HD;

    dim3 gemm_grid(2, (NN + 127) / 128);   // BN=128 -> 2 col blocks
    const int spmm_grid = (NN + 7) / 8;

    // ----- prep: converts + CSR -----
    convX_kernel<<<(int)(((size_t)NN * FIN / 2 + TB - 1) / TB), TB>>>(x, a16, (size_t)NN * FIN);
    splitW_kernel<<<(FIN * HD + TB - 1) / TB, TB>>>(W1, wt + 0 * WSTRIDE, FIN, HD);
    splitW_kernel<<<(HD * HD + TB - 1) / TB, TB>>>(W2, wt + 1 * WSTRIDE, HD, HD);
    zero_deg_kernel<<<(NN + TB - 1) / TB, TB>>>();
    count_kernel<<<(EE + TB - 1) / TB, TB>>>(dst);
    partial_kernel<<<NPART, 1024>>>();
    scanpart_kernel<<<1, 128>>>();
    apply_kernel<<<NPART, 1024>>>();
    scatter_kernel<<<(EE + TB - 1) / TB, TB>>>(src, dst);

    // ----- layer 1: S1 = Agg(x16) [N,128]; H1 = relu(S1@W1 + b1) -----
    spmm16_128_kernel<<<spmm_grid, 256>>>(a16, t16);
    gemm_mma2_kernel<<<gemm_grid, 256, GSMEM>>>(t16, wt + 0 * WSTRIDE, b1, a16, NN, FIN);
    // ----- layer 2 -----
    spmm16_256_kernel<<<spmm_grid, 256>>>(a16, t16);
    gemm_mma2_kernel<<<gemm_grid, 256, GSMEM>>>(t16, wt + 1 * WSTRIDE, b2, a16, NN, HD);
    // ----- layer 3: S3 = Agg(H2); pool; then tiny GEMMs -----
    spmm16_256_kernel<<<spmm_grid, 256>>>(a16, t16);
    bounds_kernel<<<(NN + TB - 1) / TB, TB>>>(batch);
    pool16_kernel<<<GG, HD>>>(t16);

    // ----- head (fp32) -----
    dim3 g3(HD / 64, GG / 64);
    gemm64_kernel<false><<<g3, 256>>>(pooled, W3, b3, o3, GG, HD, HD);
    dim3 gm1(NHID_ / 64, GG / 64);
    gemm64_kernel<true><<<gm1, 256>>>(o3, Wm1, bm1, mlp1, GG, HD, NHID_);
    dim3 gm2(NOUT_ / 64, GG / 64);
    gemm64_kernel<false><<<gm2, 256>>>(mlp1, Wm2, bm2, out, GG, NHID_, NOUT_);
}